// round 5
// baseline (speedup 1.0000x reference)
#include <cuda_runtime.h>
#include <math.h>

// Problem constants
#define BQ 8
#define TT 2048
#define DD 512
#define SDIM 256
#define ODIM 64
#define MM (BQ*TT)          // 16384 rows
#define N1 768              // padded 704 (gate 0-255 | in 256-511 | v 512-575 | k 576-639 | q 640-703)
#define KC2 320             // states(256) + bind(64)
#define NCH 64              // scan chunks of 32
#define CHK 32
#define CB 64               // binding chunk
#define NCB 32

// ---------------- device scratch (no runtime allocation) ----------------
__device__ float g_W1[DD*N1];             // transposed [N1][DD], k-permuted
__device__ float g_b1[N1];
__device__ float g_Xc[(size_t)MM*DD];     // tf32-rounded, k-permuted copy of x
__device__ float g_Z[(size_t)MM*N1];
__device__ float g_W2[KC2*DD];            // transposed [DD][KC2], k-permuted
__device__ float g_b2[DD];
__device__ float g_A2[(size_t)MM*KC2];    // tf32-rounded, k-permuted
__device__ float g_Y[(size_t)MM*DD];
__device__ float g_sumA[BQ*NCH*SDIM];
__device__ float g_sumB[BQ*NCH*SDIM];
__device__ float g_hpr[BQ*NCH*SDIM];
__device__ float g_Mc[(size_t)BQ*NCB*ODIM*ODIM];
__device__ float g_Sc[(size_t)BQ*NCB*ODIM*ODIM];
__device__ float g_pw[65*ODIM];

__device__ __forceinline__ float sigm_acc(float z){ return 1.0f/(1.0f+expf(-z)); }
__device__ __forceinline__ float sigm(float z){ return 1.0f/(1.0f+__expf(-z)); }

__device__ __forceinline__ unsigned f2tf(float x){
    unsigned r; asm("cvt.rna.tf32.f32 %0, %1;" : "=r"(r) : "f"(x)); return r;
}
__device__ __forceinline__ float tfr(float x){ return __uint_as_float(f2tf(x)); }

// k-permutation within each 16-group: pairs (c, c+4) become adjacent
__device__ __forceinline__ int perm16(int c){
    int c7 = c & 7;
    return (c & 8) | ((c7 & 3) << 1) | (c7 >> 2);
}
// inverse: original column for permuted position p
__device__ __forceinline__ int invp16(int p){
    int p7 = p & 7;
    return (p & 8) | ((p7 & 1) << 2) | (p7 >> 1);
}

// ---------------- prep kernels ----------------
// W1 transposed [n][d], k(d)-permuted, tf32-rounded
__global__ void pack_w1(const float* __restrict__ gW, const float* __restrict__ gb,
                        const float* __restrict__ iW, const float* __restrict__ ib,
                        const float* __restrict__ vW, const float* __restrict__ vb,
                        const float* __restrict__ kW, const float* __restrict__ kb,
                        const float* __restrict__ qW, const float* __restrict__ qb)
{
    int idx = blockIdx.x*256 + threadIdx.x;     // over N1*DD
    if (idx < N1*DD) {
        int n = idx >> 9, d = idx & 511;
        float w = 0.f;
        if      (n < 256) w = gW[d*256 + n];
        else if (n < 512) w = iW[d*256 + (n-256)];
        else if (n < 576) w = vW[d*64 + (n-512)];
        else if (n < 640) w = kW[d*64 + (n-576)];
        else if (n < 704) w = qW[d*64 + (n-640)];
        g_W1[(size_t)n*DD + (d & ~15) + perm16(d & 15)] = tfr(w);
    }
    if (idx < N1) {
        float b = 0.f;
        if      (idx < 256) b = gb[idx];
        else if (idx < 512) b = ib[idx-256];
        else if (idx < 576) b = vb[idx-512];
        else if (idx < 640) b = kb[idx-576];
        else if (idx < 704) b = qb[idx-640];
        g_b1[idx] = b;
    }
}

// W2 transposed [n][k], k-permuted, tf32-rounded. n in [0,512), k in [0,320)
__global__ void pack_w2(const float* __restrict__ oW, const float* __restrict__ ob,
                        const float* __restrict__ pW, const float* __restrict__ pb)
{
    int idx = blockIdx.x*256 + threadIdx.x;
    if (idx < DD*KC2) {
        int n = idx / KC2, k = idx % KC2;
        float w = (k < 256) ? oW[k*DD + n] : pW[(k-256)*DD + n];
        g_W2[(size_t)n*KC2 + (k & ~15) + perm16(k & 15)] = tfr(w);
    }
    if (idx < DD) g_b2[idx] = ob[idx] + pb[idx];
}

// tf32-round + k-permute x into g_Xc. Each thread writes 4 consecutive permuted slots.
__global__ void cvt_x(const float* __restrict__ x)
{
    size_t i4 = (size_t)blockIdx.x*256 + threadIdx.x;
    size_t base = i4*4;
    size_t g16 = base & ~(size_t)15;
    int off = (int)(base & 15);
    float4 v;
    v.x = tfr(x[g16 + invp16(off+0)]);
    v.y = tfr(x[g16 + invp16(off+1)]);
    v.z = tfr(x[g16 + invp16(off+2)]);
    v.w = tfr(x[g16 + invp16(off+3)]);
    ((float4*)g_Xc)[i4] = v;
}

__global__ void pw_kernel(const float* __restrict__ op_decay)
{
    int i = threadIdx.x;
    if (i < ODIM) {
        float d = sigm_acc(op_decay[i]);
        float p = 1.f;
        for (int e = 0; e <= 64; e++) { g_pw[e*ODIM + i] = p; p *= d; }
    }
}

// ---------------- tf32 tensor-core GEMM ----------------
// C[M,N] = A[M,K] @ Bt[N,K]^T + bias (+addsrc). A,Bt k-permuted + pre-rounded.
// 128x128x16 tile, 3-stage cp.async, 256 thr, warp tile 64x32, m16n8k8.
#define AST 20
#define STAGE_F (128*AST)

__device__ __forceinline__ void mma_tf32(float* c, const unsigned* a, const unsigned* b){
    asm volatile(
      "mma.sync.aligned.m16n8k8.row.col.f32.tf32.tf32.f32 "
      "{%0,%1,%2,%3}, {%4,%5,%6,%7}, {%8,%9}, {%0,%1,%2,%3};\n"
      : "+f"(c[0]), "+f"(c[1]), "+f"(c[2]), "+f"(c[3])
      : "r"(a[0]), "r"(a[1]), "r"(a[2]), "r"(a[3]), "r"(b[0]), "r"(b[1]));
}
__device__ __forceinline__ void cpa16(void* dst, const void* src){
    unsigned d = (unsigned)__cvta_generic_to_shared(dst);
    asm volatile("cp.async.cg.shared.global [%0], [%1], 16;" :: "r"(d), "l"(src));
}

__global__ void __launch_bounds__(256,2) gemm_tf32(
    const float* __restrict__ A, int lda,
    const float* __restrict__ Bt, int ldb,
    const float* __restrict__ bias,
    const float* __restrict__ addsrc, int ldadd,
    float* __restrict__ C, int ldc, int K)
{
    extern __shared__ float sm[];
    float* AsBase = sm;                 // [3][128][AST]
    float* BsBase = sm + 3*STAGE_F;     // [3][128][AST]

    int tid  = threadIdx.x;
    int lane = tid & 31, warp = tid >> 5;
    int wm = (warp >> 2) * 64;
    int wn = (warp & 3) * 32;
    int lr = lane >> 2;
    int lc = lane & 3;

    size_t rowBase = (size_t)blockIdx.y * 128;
    int colBase = blockIdx.x * 128;

    // per-tile: 512 chunks for A + 512 for B, 2 of each per thread
    int ac0 = tid, ac1 = tid + 256;
    int r0 = ac0 >> 2, kc0 = (ac0 & 3) * 4;
    int r1 = ac1 >> 2, kc1 = (ac1 & 3) * 4;

    float acc[4][4][4];
    #pragma unroll
    for (int i = 0; i < 4; i++)
        #pragma unroll
        for (int j = 0; j < 4; j++)
            #pragma unroll
            for (int u = 0; u < 4; u++) acc[i][j][u] = 0.f;

    int nIter = K / 16;

    auto issueTile = [&](int st, int k0){
        float* Asp = AsBase + st*STAGE_F;
        float* Bsp = BsBase + st*STAGE_F;
        cpa16(Asp + r0*AST + kc0, A + (rowBase + r0)*lda + k0 + kc0);
        cpa16(Asp + r1*AST + kc1, A + (rowBase + r1)*lda + k0 + kc1);
        cpa16(Bsp + r0*AST + kc0, Bt + (size_t)(colBase + r0)*ldb + k0 + kc0);
        cpa16(Bsp + r1*AST + kc1, Bt + (size_t)(colBase + r1)*ldb + k0 + kc1);
    };

    issueTile(0, 0);
    asm volatile("cp.async.commit_group;");
    issueTile(1, 16);
    asm volatile("cp.async.commit_group;");

    for (int it = 0; it < nIter; it++) {
        asm volatile("cp.async.wait_group 1;");
        __syncthreads();

        int nx = it + 2;
        if (nx < nIter) issueTile(nx % 3, nx * 16);
        asm volatile("cp.async.commit_group;");

        const float* Asp = AsBase + (it % 3)*STAGE_F;
        const float* Bsp = BsBase + (it % 3)*STAGE_F;

        #pragma unroll
        for (int kk = 0; kk < 16; kk += 8) {
            unsigned af[4][4], bf[4][2];
            #pragma unroll
            for (int mt = 0; mt < 4; mt++) {
                int m0 = wm + mt*16 + lr;
                float2 a0 = *(const float2*)(Asp + m0*AST + kk + lc*2);
                float2 a1 = *(const float2*)(Asp + (m0+8)*AST + kk + lc*2);
                af[mt][0] = __float_as_uint(a0.x);
                af[mt][1] = __float_as_uint(a1.x);
                af[mt][2] = __float_as_uint(a0.y);
                af[mt][3] = __float_as_uint(a1.y);
            }
            #pragma unroll
            for (int nt = 0; nt < 4; nt++) {
                int n0 = wn + nt*8 + lr;
                float2 b0 = *(const float2*)(Bsp + n0*AST + kk + lc*2);
                bf[nt][0] = __float_as_uint(b0.x);
                bf[nt][1] = __float_as_uint(b0.y);
            }
            #pragma unroll
            for (int mt = 0; mt < 4; mt++)
                #pragma unroll
                for (int nt = 0; nt < 4; nt++)
                    mma_tf32(acc[mt][nt], af[mt], bf[nt]);
        }
        __syncthreads();
    }

    // epilogue
    #pragma unroll
    for (int mt = 0; mt < 4; mt++) {
        size_t row0 = rowBase + wm + mt*16 + lr;
        #pragma unroll
        for (int nt = 0; nt < 4; nt++) {
            int col = colBase + wn + nt*8 + lc*2;
            float b0 = bias[col], b1 = bias[col+1];
            float a00=0.f,a01=0.f,a10=0.f,a11=0.f;
            if (addsrc) {
                const float* p0 = addsrc + row0*(size_t)ldadd + col;
                const float* p1 = addsrc + (row0+8)*(size_t)ldadd + col;
                a00 = p0[0]; a01 = p0[1]; a10 = p1[0]; a11 = p1[1];
            }
            float2 q0 = make_float2(acc[mt][nt][0] + b0 + a00, acc[mt][nt][1] + b1 + a01);
            float2 q1 = make_float2(acc[mt][nt][2] + b0 + a10, acc[mt][nt][3] + b1 + a11);
            *(float2*)(C + row0*(size_t)ldc + col)     = q0;
            *(float2*)(C + (row0+8)*(size_t)ldc + col) = q1;
        }
    }
}

// ---------------- gated scan ----------------
__global__ void scan_summ()
{
    int bc = blockIdx.x;               // 0..511
    int b = bc >> 6, c = bc & 63;
    int sd = threadIdx.x;
    size_t base = ((size_t)(b*TT + c*CHK))*N1 + sd;
    float ca = 1.f, wb = 0.f;
    for (int k = 0; k < CHK; k++) {
        float zg = g_Z[base + (size_t)k*N1];
        float zi = g_Z[base + (size_t)k*N1 + SDIM];
        float a = sigm(zg);
        float bb = (1.f - a)*zi;
        ca *= a;
        wb += __fdividef(bb, fmaxf(ca, 1e-8f));
    }
    int idx = bc*SDIM + sd;
    g_sumA[idx] = ca; g_sumB[idx] = wb;
}

__global__ void scan_carry()
{
    int b = blockIdx.x;
    int sd = threadIdx.x;
    float h = 0.f;
    for (int c = 0; c < NCH; c++) {
        int idx = (b*NCH + c)*SDIM + sd;
        g_hpr[idx] = h;
        h = g_sumA[idx]*(h + g_sumB[idx]);
    }
}

__global__ void scan_states()
{
    int bc = blockIdx.x;
    int b = bc >> 6, c = bc & 63;
    int sd = threadIdx.x;
    size_t zb = ((size_t)(b*TT + c*CHK))*N1 + sd;
    int sdp = (sd & ~15) | perm16(sd & 15);
    size_t ob = ((size_t)(b*TT + c*CHK))*KC2 + sdp;
    float h = g_hpr[bc*SDIM + sd];
    float ca = 1.f, wb = 0.f;
    for (int k = 0; k < CHK; k++) {
        float zg = g_Z[zb + (size_t)k*N1];
        float zi = g_Z[zb + (size_t)k*N1 + SDIM];
        float a = sigm(zg);
        float bb = (1.f - a)*zi;
        ca *= a;
        wb += __fdividef(bb, fmaxf(ca, 1e-8f));
        g_A2[ob + (size_t)k*KC2] = tfr(ca*(h + wb));
    }
}

// ---------------- binding scan ----------------
__global__ void bind_chunksum()
{
    __shared__ float Vs[CB*ODIM];
    __shared__ float Ks[CB*ODIM];
    int b = blockIdx.x >> 5, c = blockIdx.x & 31;
    int tid = threadIdx.x;
    int j = tid >> 2, q0 = (tid & 3)*16;
    size_t zrow = ((size_t)(b*TT + c*CB + j))*N1;
    #pragma unroll
    for (int u = 0; u < 4; u++) {
        float4 vv = *(const float4*)&g_Z[zrow + 512 + q0 + u*4];
        float4 pp = *(const float4*)&g_pw[(63-j)*ODIM + q0 + u*4];
        vv.x *= pp.x; vv.y *= pp.y; vv.z *= pp.z; vv.w *= pp.w;
        *(float4*)&Vs[j*ODIM + q0 + u*4] = vv;
        float4 kk = *(const float4*)&g_Z[zrow + 576 + q0 + u*4];
        *(float4*)&Ks[j*ODIM + q0 + u*4] = kk;
    }
    __syncthreads();
    int i = tid >> 2, l0 = (tid & 3)*16;
    float acc[16] = {};
    for (int jj = 0; jj < CB; jj++) {
        float vv = Vs[jj*ODIM + i];
        #pragma unroll
        for (int u = 0; u < 16; u += 4) {
            float4 k4 = *(const float4*)&Ks[jj*ODIM + l0 + u];
            acc[u+0] += vv*k4.x; acc[u+1] += vv*k4.y;
            acc[u+2] += vv*k4.z; acc[u+3] += vv*k4.w;
        }
    }
    size_t mb = ((size_t)(b*NCB + c))*ODIM*ODIM + i*ODIM + l0;
    #pragma unroll
    for (int u = 0; u < 16; u += 4)
        *(float4*)&g_Mc[mb + u] = make_float4(acc[u], acc[u+1], acc[u+2], acc[u+3]);
}

__global__ void bind_carry()
{
    int gid = blockIdx.x*blockDim.x + threadIdx.x;   // 32768 lanes
    int b = gid >> 12, e = gid & 4095, i = e >> 6;
    float p64 = g_pw[64*ODIM + i];
    float s = 0.f;
    size_t base = (size_t)b*NCB*4096 + e;
    for (int c = 0; c < NCB; c++) {
        g_Sc[base + (size_t)c*4096] = s;
        s = p64*s + g_Mc[base + (size_t)c*4096];
    }
}

__global__ void bind_out()
{
    extern __shared__ float sm[];
    float* Qs  = sm;            // [64][65]  Q[t][l]
    float* KT  = sm + 4160;     // [64][64]  K^T[l][j] -> later Cq[t][i]
    float* SV  = sm + 8256;     // [64][64]  S^T[l][i] -> later V[j][i]
    float* As  = sm + 12352;    // [64][65]  A[t][j]
    float* pws = sm + 16512;    // [65][64]
    int b = blockIdx.x >> 5, c = blockIdx.x & 31;
    int tid = threadIdx.x;
    int t = tid >> 2, q0 = (tid & 3)*16;
    size_t zrow = ((size_t)(b*TT + c*CB + t))*N1;
    size_t srow = ((size_t)(b*NCB + c))*4096 + t*ODIM;
    #pragma unroll
    for (int u = 0; u < 4; u++) {
        float4 qv = *(const float4*)&g_Z[zrow + 640 + q0 + u*4];
        Qs[t*65 + q0+u*4+0] = qv.x; Qs[t*65 + q0+u*4+1] = qv.y;
        Qs[t*65 + q0+u*4+2] = qv.z; Qs[t*65 + q0+u*4+3] = qv.w;
        float4 kv = *(const float4*)&g_Z[zrow + 576 + q0 + u*4];     // t plays "j"
        KT[(q0+u*4+0)*ODIM + t] = kv.x; KT[(q0+u*4+1)*ODIM + t] = kv.y;
        KT[(q0+u*4+2)*ODIM + t] = kv.z; KT[(q0+u*4+3)*ODIM + t] = kv.w;
        float4 sv = *(const float4*)&g_Sc[srow + q0 + u*4];          // t plays "i"
        SV[(q0+u*4+0)*ODIM + t] = sv.x; SV[(q0+u*4+1)*ODIM + t] = sv.y;
        SV[(q0+u*4+2)*ODIM + t] = sv.z; SV[(q0+u*4+3)*ODIM + t] = sv.w;
    }
    for (int idx = tid; idx < 65*ODIM; idx += 256) pws[idx] = g_pw[idx];
    __syncthreads();

    float accA[16] = {}, accC[16] = {};
    for (int l = 0; l < ODIM; l++) {
        float q = Qs[t*65 + l];
        #pragma unroll
        for (int u = 0; u < 16; u += 4) {
            float4 k4 = *(const float4*)&KT[l*ODIM + q0 + u];
            float4 s4 = *(const float4*)&SV[l*ODIM + q0 + u];
            accA[u+0] += q*k4.x; accA[u+1] += q*k4.y; accA[u+2] += q*k4.z; accA[u+3] += q*k4.w;
            accC[u+0] += q*s4.x; accC[u+1] += q*s4.y; accC[u+2] += q*s4.z; accC[u+3] += q*s4.w;
        }
    }
    __syncthreads();
    #pragma unroll
    for (int u = 0; u < 16; u++) As[t*65 + q0 + u] = accA[u];
    #pragma unroll
    for (int u = 0; u < 16; u += 4)
        *(float4*)&KT[t*ODIM + q0 + u] = make_float4(accC[u], accC[u+1], accC[u+2], accC[u+3]);
    #pragma unroll
    for (int u = 0; u < 4; u++) {
        float4 vv = *(const float4*)&g_Z[zrow + 512 + q0 + u*4];     // t plays "j"
        *(float4*)&SV[t*ODIM + q0 + u*4] = vv;
    }
    __syncthreads();

    float o[16];
    #pragma unroll
    for (int u = 0; u < 16; u++)
        o[u] = pws[(t+1)*ODIM + q0 + u] * KT[t*ODIM + q0 + u];
    for (int j = 0; j <= t; j++) {
        float a = As[t*65 + j];
        int d = t - j;
        #pragma unroll
        for (int u = 0; u < 16; u += 4) {
            float4 p4 = *(const float4*)&pws[d*ODIM + q0 + u];
            float4 v4 = *(const float4*)&SV[j*ODIM + q0 + u];
            o[u+0] += a*p4.x*v4.x; o[u+1] += a*p4.y*v4.y;
            o[u+2] += a*p4.z*v4.z; o[u+3] += a*p4.w*v4.w;
        }
    }
    // permute k within the 16-group, round, write as 4 float4
    float op[16];
    #pragma unroll
    for (int u = 0; u < 16; u++) op[perm16(u)] = tfr(o[u]);
    size_t orow = ((size_t)(b*TT + c*CB + t))*KC2 + SDIM + q0;
    #pragma unroll
    for (int u = 0; u < 16; u += 4)
        *(float4*)&g_A2[orow + u] = make_float4(op[u], op[u+1], op[u+2], op[u+3]);
}

// ---------------- layernorm: warp per row ----------------
__global__ void ln_kernel(const float* __restrict__ lng, const float* __restrict__ lnb,
                          float* __restrict__ out)
{
    int row = blockIdx.x*8 + (threadIdx.x >> 5);
    int lane = threadIdx.x & 31;
    const float4* y4 = (const float4*)(g_Y + (size_t)row*DD);
    float4 v[4];
    float s = 0.f, s2 = 0.f;
    #pragma unroll
    for (int u = 0; u < 4; u++) {
        v[u] = y4[lane + u*32];
        s  += v[u].x + v[u].y + v[u].z + v[u].w;
        s2 += v[u].x*v[u].x + v[u].y*v[u].y + v[u].z*v[u].z + v[u].w*v[u].w;
    }
    #pragma unroll
    for (int off = 16; off; off >>= 1) {
        s  += __shfl_xor_sync(0xffffffffu, s,  off);
        s2 += __shfl_xor_sync(0xffffffffu, s2, off);
    }
    float mu  = s * (1.f/512.f);
    float var = s2 * (1.f/512.f) - mu*mu;
    float inv = rsqrtf(var + 1e-5f);
    float4* o4 = (float4*)(out + (size_t)row*DD);
    const float4* g4 = (const float4*)lng;
    const float4* b4 = (const float4*)lnb;
    #pragma unroll
    for (int u = 0; u < 4; u++) {
        float4 gg = g4[lane + u*32];
        float4 bb = b4[lane + u*32];
        float4 r;
        r.x = (v[u].x - mu)*inv*gg.x + bb.x;
        r.y = (v[u].y - mu)*inv*gg.y + bb.y;
        r.z = (v[u].z - mu)*inv*gg.z + bb.z;
        r.w = (v[u].w - mu)*inv*gg.w + bb.w;
        o4[lane + u*32] = r;
    }
}

// ---------------- host launch ----------------
extern "C" void kernel_launch(void* const* d_in, const int* in_sizes, int n_in,
                              void* d_out, int out_size)
{
    const float* x       = (const float*)d_in[0];
    const float* gate_W  = (const float*)d_in[1];
    const float* gate_b  = (const float*)d_in[2];
    const float* in_W    = (const float*)d_in[3];
    const float* in_b    = (const float*)d_in[4];
    const float* out_W   = (const float*)d_in[5];
    const float* out_b   = (const float*)d_in[6];
    const float* opv_W   = (const float*)d_in[7];
    const float* opv_b   = (const float*)d_in[8];
    const float* opk_W   = (const float*)d_in[9];
    const float* opk_b   = (const float*)d_in[10];
    const float* opq_W   = (const float*)d_in[11];
    const float* opq_b   = (const float*)d_in[12];
    const float* op_decay= (const float*)d_in[13];
    const float* opout_W = (const float*)d_in[14];
    const float* opout_b = (const float*)d_in[15];
    const float* ln_g    = (const float*)d_in[16];
    const float* ln_b    = (const float*)d_in[17];
    float* out = (float*)d_out;

    void *pW1, *pb1, *pZ, *pW2, *pb2, *pA2, *pY, *pXc;
    cudaGetSymbolAddress(&pW1, g_W1);
    cudaGetSymbolAddress(&pb1, g_b1);
    cudaGetSymbolAddress(&pZ,  g_Z);
    cudaGetSymbolAddress(&pW2, g_W2);
    cudaGetSymbolAddress(&pb2, g_b2);
    cudaGetSymbolAddress(&pA2, g_A2);
    cudaGetSymbolAddress(&pY,  g_Y);
    cudaGetSymbolAddress(&pXc, g_Xc);

    int gemmSmem = 2*3*STAGE_F*4;   // 61440 B
    cudaFuncSetAttribute(gemm_tf32, cudaFuncAttributeMaxDynamicSharedMemorySize, gemmSmem);
    cudaFuncSetAttribute(bind_out, cudaFuncAttributeMaxDynamicSharedMemorySize, 20672*4);

    // prep
    pack_w1<<<(N1*DD + 255)/256, 256>>>(gate_W, gate_b, in_W, in_b,
                                        opv_W, opv_b, opk_W, opk_b, opq_W, opq_b);
    pack_w2<<<(DD*KC2 + 255)/256, 256>>>(out_W, out_b, opout_W, opout_b);
    pw_kernel<<<1, 64>>>(op_decay);
    cvt_x<<<(MM*DD/4)/256, 256>>>(x);

    // GEMM-1: Z = Xc @ W1t^T + b1
    gemm_tf32<<<dim3(N1/128, MM/128), 256, gemmSmem>>>(
        (const float*)pXc, DD, (const float*)pW1, DD, (const float*)pb1,
        nullptr, 0, (float*)pZ, N1, DD);

    // gated scan
    scan_summ<<<BQ*NCH, SDIM>>>();
    scan_carry<<<BQ, SDIM>>>();
    scan_states<<<BQ*NCH, SDIM>>>();

    // binding scan
    bind_chunksum<<<BQ*NCB, 256>>>();
    bind_carry<<<BQ*NCB*16/32, 256>>>();
    bind_out<<<BQ*NCB, 256, 20672*4>>>();

    // GEMM-2: Y = A2 @ W2t^T + b2 + x
    gemm_tf32<<<dim3(DD/128, MM/128), 256, gemmSmem>>>(
        (const float*)pA2, KC2, (const float*)pW2, KC2, (const float*)pb2,
        x, DD, (float*)pY, DD, KC2);

    // layernorm -> out
    ln_kernel<<<MM/8, 256>>>(ln_g, ln_b, out);
}

// round 11
// speedup vs baseline: 1.1149x; 1.1149x over previous
#include <cuda_runtime.h>
#include <math.h>

// Problem constants
#define BQ 8
#define TT 2048
#define DD 512
#define SDIM 256
#define ODIM 64
#define MM (BQ*TT)          // 16384 rows
#define N1 768              // padded 704 (gate 0-255 | in 256-511 | v 512-575 | k 576-639 | q 640-703)
#define KC2 320             // states(256) + bind(64)
#define NCH 64              // scan chunks of 32
#define CHK 32
#define CB 64               // binding chunk
#define NCB 32

// ---------------- device scratch (no runtime allocation) ----------------
__device__ float g_W1[DD*N1];
__device__ float g_b1[N1];
__device__ float g_Xc[(size_t)MM*DD];     // tf32-rounded copy of x
__device__ float g_Z[(size_t)MM*N1];
__device__ float g_W2[KC2*DD];
__device__ float g_b2[DD];
__device__ float g_A2[(size_t)MM*KC2];    // written pre-rounded to tf32
__device__ float g_Y[(size_t)MM*DD];
__device__ float g_sumA[BQ*NCH*SDIM];
__device__ float g_sumB[BQ*NCH*SDIM];
__device__ float g_hpr[BQ*NCH*SDIM];
__device__ float g_Mc[(size_t)BQ*NCB*ODIM*ODIM];
__device__ float g_Sc[(size_t)BQ*NCB*ODIM*ODIM];
__device__ float g_pw[65*ODIM];

__device__ __forceinline__ float sigm_acc(float z){ return 1.0f/(1.0f+expf(-z)); }

__device__ __forceinline__ unsigned f2tf(float x){
    unsigned r; asm("cvt.rna.tf32.f32 %0, %1;" : "=r"(r) : "f"(x)); return r;
}
__device__ __forceinline__ float tfr(float x){ return __uint_as_float(f2tf(x)); }

// ---------------- prep kernels ----------------
__global__ void pack_w1(const float* __restrict__ gW, const float* __restrict__ gb,
                        const float* __restrict__ iW, const float* __restrict__ ib,
                        const float* __restrict__ vW, const float* __restrict__ vb,
                        const float* __restrict__ kW, const float* __restrict__ kb,
                        const float* __restrict__ qW, const float* __restrict__ qb)
{
    int idx = blockIdx.x*256 + threadIdx.x;
    if (idx < DD*N1) {
        int d = idx / N1, n = idx % N1;
        float w = 0.f;
        if      (n < 256) w = gW[d*256 + n];
        else if (n < 512) w = iW[d*256 + (n-256)];
        else if (n < 576) w = vW[d*64 + (n-512)];
        else if (n < 640) w = kW[d*64 + (n-576)];
        else if (n < 704) w = qW[d*64 + (n-640)];
        g_W1[idx] = tfr(w);
    }
    if (idx < N1) {
        float b = 0.f;
        if      (idx < 256) b = gb[idx];
        else if (idx < 512) b = ib[idx-256];
        else if (idx < 576) b = vb[idx-512];
        else if (idx < 640) b = kb[idx-576];
        else if (idx < 704) b = qb[idx-640];
        g_b1[idx] = b;
    }
}

__global__ void pack_w2(const float* __restrict__ oW, const float* __restrict__ ob,
                        const float* __restrict__ pW, const float* __restrict__ pb)
{
    int idx = blockIdx.x*256 + threadIdx.x;
    if (idx < KC2*DD) {
        int r = idx / DD, c = idx % DD;
        g_W2[idx] = tfr((r < 256) ? oW[r*DD + c] : pW[(r-256)*DD + c]);
    }
    if (idx < DD) g_b2[idx] = ob[idx] + pb[idx];
}

// tf32-round x into g_Xc (float4 per thread)
__global__ void cvt_x(const float* __restrict__ x)
{
    size_t i4 = (size_t)blockIdx.x*256 + threadIdx.x;
    float4 v = ((const float4*)x)[i4];
    v.x = tfr(v.x); v.y = tfr(v.y); v.z = tfr(v.z); v.w = tfr(v.w);
    ((float4*)g_Xc)[i4] = v;
}

__global__ void pw_kernel(const float* __restrict__ op_decay)
{
    int i = threadIdx.x;
    if (i < ODIM) {
        float d = sigm_acc(op_decay[i]);
        float p = 1.f;
        for (int e = 0; e <= 64; e++) { g_pw[e*ODIM + i] = p; p *= d; }
    }
}

// ---------------- tf32 tensor-core GEMM (R4 proven config) ----------------
#define ASTRIDE 20
#define BSTRIDE 136

__device__ __forceinline__ void mma_tf32(float* c, const unsigned* a, const unsigned* b){
    asm volatile(
      "mma.sync.aligned.m16n8k8.row.col.f32.tf32.tf32.f32 "
      "{%0,%1,%2,%3}, {%4,%5,%6,%7}, {%8,%9}, {%0,%1,%2,%3};\n"
      : "+f"(c[0]), "+f"(c[1]), "+f"(c[2]), "+f"(c[3])
      : "r"(a[0]), "r"(a[1]), "r"(a[2]), "r"(a[3]), "r"(b[0]), "r"(b[1]));
}
__device__ __forceinline__ void cpa16(void* dst, const void* src){
    unsigned d = (unsigned)__cvta_generic_to_shared(dst);
    asm volatile("cp.async.cg.shared.global [%0], [%1], 16;" :: "r"(d), "l"(src));
}

__global__ void __launch_bounds__(256,2) gemm_tf32(
    const float* __restrict__ A, int lda,
    const float* __restrict__ Bw, int ldb,
    const float* __restrict__ bias,
    const float* __restrict__ addsrc, int ldadd,
    float* __restrict__ C, int ldc, int K)
{
    __shared__ float As[2][128][ASTRIDE];   // [m][k] padded
    __shared__ float Bs[2][16][BSTRIDE];    // [k][n] padded

    int tid  = threadIdx.x;
    int lane = tid & 31, warp = tid >> 5;
    int wm = (warp >> 2) * 64;
    int wn = (warp & 3) * 32;
    int lr = lane >> 2;
    int lc = lane & 3;

    size_t rowBase = (size_t)blockIdx.y * 128;
    int colBase = blockIdx.x * 128;

    int ac0 = tid, ac1 = tid + 256;

    float acc[4][4][4];
    #pragma unroll
    for (int i = 0; i < 4; i++)
        #pragma unroll
        for (int j = 0; j < 4; j++)
            #pragma unroll
            for (int u = 0; u < 4; u++) acc[i][j][u] = 0.f;

    int nIter = K / 16;

    {
        int r0 = ac0 >> 2, kc0 = (ac0 & 3) * 4;
        int r1 = ac1 >> 2, kc1 = (ac1 & 3) * 4;
        cpa16(&As[0][r0][kc0], A + (rowBase + r0)*lda + kc0);
        cpa16(&As[0][r1][kc1], A + (rowBase + r1)*lda + kc1);
        int br0 = ac0 >> 5, bn0 = (ac0 & 31) * 4;
        int br1 = ac1 >> 5, bn1 = (ac1 & 31) * 4;
        cpa16(&Bs[0][br0][bn0], Bw + (size_t)br0*ldb + colBase + bn0);
        cpa16(&Bs[0][br1][bn1], Bw + (size_t)br1*ldb + colBase + bn1);
        asm volatile("cp.async.commit_group;");
    }

    int buf = 0;
    for (int it = 0; it < nIter; it++) {
        asm volatile("cp.async.wait_group 0;");
        __syncthreads();

        if (it + 1 < nIter) {
            int k0 = (it + 1) * 16;
            int nb = buf ^ 1;
            int r0 = ac0 >> 2, kc0 = (ac0 & 3) * 4;
            int r1 = ac1 >> 2, kc1 = (ac1 & 3) * 4;
            cpa16(&As[nb][r0][kc0], A + (rowBase + r0)*lda + k0 + kc0);
            cpa16(&As[nb][r1][kc1], A + (rowBase + r1)*lda + k0 + kc1);
            int br0 = ac0 >> 5, bn0 = (ac0 & 31) * 4;
            int br1 = ac1 >> 5, bn1 = (ac1 & 31) * 4;
            cpa16(&Bs[nb][br0][bn0], Bw + (size_t)(k0+br0)*ldb + colBase + bn0);
            cpa16(&Bs[nb][br1][bn1], Bw + (size_t)(k0+br1)*ldb + colBase + bn1);
            asm volatile("cp.async.commit_group;");
        }

        #pragma unroll
        for (int kk = 0; kk < 16; kk += 8) {
            unsigned af[4][4], bf[4][2];
            #pragma unroll
            for (int mt = 0; mt < 4; mt++) {
                int m0 = wm + mt*16 + lr;
                af[mt][0] = __float_as_uint(As[buf][m0    ][kk + lc]);
                af[mt][1] = __float_as_uint(As[buf][m0 + 8][kk + lc]);
                af[mt][2] = __float_as_uint(As[buf][m0    ][kk + lc + 4]);
                af[mt][3] = __float_as_uint(As[buf][m0 + 8][kk + lc + 4]);
            }
            #pragma unroll
            for (int nt = 0; nt < 4; nt++) {
                int n0 = wn + nt*8 + lr;
                bf[nt][0] = __float_as_uint(Bs[buf][kk + lc    ][n0]);
                bf[nt][1] = __float_as_uint(Bs[buf][kk + lc + 4][n0]);
            }
            #pragma unroll
            for (int mt = 0; mt < 4; mt++)
                #pragma unroll
                for (int nt = 0; nt < 4; nt++)
                    mma_tf32(acc[mt][nt], af[mt], bf[nt]);
        }
        buf ^= 1;
    }

    // epilogue
    #pragma unroll
    for (int mt = 0; mt < 4; mt++) {
        size_t row0 = rowBase + wm + mt*16 + lr;
        #pragma unroll
        for (int nt = 0; nt < 4; nt++) {
            int col = colBase + wn + nt*8 + lc*2;
            float b0 = bias[col], b1 = bias[col+1];
            float a00=0.f,a01=0.f,a10=0.f,a11=0.f;
            if (addsrc) {
                const float* p0 = addsrc + row0*(size_t)ldadd + col;
                const float* p1 = addsrc + (row0+8)*(size_t)ldadd + col;
                a00 = p0[0]; a01 = p0[1]; a10 = p1[0]; a11 = p1[1];
            }
            float2 r0 = make_float2(acc[mt][nt][0] + b0 + a00, acc[mt][nt][1] + b1 + a01);
            float2 r1 = make_float2(acc[mt][nt][2] + b0 + a10, acc[mt][nt][3] + b1 + a11);
            *(float2*)(C + row0*(size_t)ldc + col)     = r0;
            *(float2*)(C + (row0+8)*(size_t)ldc + col) = r1;
        }
    }
}

// ---------------- gated scan (reciprocal-product formulation) ----------------
// t = exp(-zg); a = 1/(1+t); 1-a = t/(1+t); rca_k = prod(1+t_j) = 1/cum_a_k.
// contribution bb/max(cum_a,1e-8):
//   rca_new <= 1e8 :  zi * t * rca_old                      (exactly bb/cum_a)
//   else           :  zi * t * rca_old * (1e8/rca_new)      (= bb*1e8)

__device__ __forceinline__ void scan_step(float zg, float zi, float& rca, float& wb)
{
    float t = __expf(-zg);
    float rca_new = rca * (1.f + t);
    float c = zi * t * rca;
    if (rca_new > 1e8f) c = zi * t * rca * __fdividef(1e8f, rca_new);
    wb += c;
    rca = rca_new;
}

__global__ void scan_summ()
{
    int bc = blockIdx.x;               // 0..511
    int b = bc >> 6, c = bc & 63;
    int sd = threadIdx.x;
    const float* zp = g_Z + ((size_t)(b*TT + c*CHK))*N1 + sd;
    float rca = 1.f, wb = 0.f;
    #pragma unroll 4
    for (int k = 0; k < CHK; k++) {
        float zg = zp[0];
        float zi = zp[SDIM];
        scan_step(zg, zi, rca, wb);
        zp += N1;
    }
    int idx = bc*SDIM + sd;
    g_sumA[idx] = __fdividef(1.f, rca);
    g_sumB[idx] = wb;
}

__global__ void scan_carry()
{
    int b = blockIdx.x;
    int sd = threadIdx.x;
    float h = 0.f;
    for (int c = 0; c < NCH; c++) {
        int idx = (b*NCH + c)*SDIM + sd;
        g_hpr[idx] = h;
        h = g_sumA[idx]*(h + g_sumB[idx]);
    }
}

__global__ void scan_states()
{
    int bc = blockIdx.x;
    int b = bc >> 6, c = bc & 63;
    int sd = threadIdx.x;
    const float* zp = g_Z + ((size_t)(b*TT + c*CHK))*N1 + sd;
    float* op = g_A2 + ((size_t)(b*TT + c*CHK))*KC2 + sd;
    float h = g_hpr[bc*SDIM + sd];
    float rca = 1.f, wb = 0.f;
    #pragma unroll 4
    for (int k = 0; k < CHK; k++) {
        float zg = zp[0];
        float zi = zp[SDIM];
        scan_step(zg, zi, rca, wb);
        *op = tfr(__fdividef(h + wb, rca));
        zp += N1; op += KC2;
    }
}

// ---------------- binding scan ----------------
__global__ void bind_chunksum()
{
    __shared__ float Vs[CB*ODIM];
    __shared__ float Ks[CB*ODIM];
    int b = blockIdx.x >> 5, c = blockIdx.x & 31;
    int tid = threadIdx.x;
    int j = tid >> 2, q0 = (tid & 3)*16;
    size_t zrow = ((size_t)(b*TT + c*CB + j))*N1;
    #pragma unroll
    for (int u = 0; u < 4; u++) {
        float4 vv = *(const float4*)&g_Z[zrow + 512 + q0 + u*4];
        float4 pp = *(const float4*)&g_pw[(63-j)*ODIM + q0 + u*4];
        vv.x *= pp.x; vv.y *= pp.y; vv.z *= pp.z; vv.w *= pp.w;
        *(float4*)&Vs[j*ODIM + q0 + u*4] = vv;
        float4 kk = *(const float4*)&g_Z[zrow + 576 + q0 + u*4];
        *(float4*)&Ks[j*ODIM + q0 + u*4] = kk;
    }
    __syncthreads();
    int i = tid >> 2, l0 = (tid & 3)*16;
    float acc[16] = {};
    for (int jj = 0; jj < CB; jj++) {
        float vv = Vs[jj*ODIM + i];
        #pragma unroll
        for (int u = 0; u < 16; u += 4) {
            float4 k4 = *(const float4*)&Ks[jj*ODIM + l0 + u];
            acc[u+0] += vv*k4.x; acc[u+1] += vv*k4.y;
            acc[u+2] += vv*k4.z; acc[u+3] += vv*k4.w;
        }
    }
    size_t mb = ((size_t)(b*NCB + c))*ODIM*ODIM + i*ODIM + l0;
    #pragma unroll
    for (int u = 0; u < 16; u += 4)
        *(float4*)&g_Mc[mb + u] = make_float4(acc[u], acc[u+1], acc[u+2], acc[u+3]);
}

__global__ void bind_carry()
{
    int gid = blockIdx.x*blockDim.x + threadIdx.x;   // 32768 lanes
    int b = gid >> 12, e = gid & 4095, i = e >> 6;
    float p64 = g_pw[64*ODIM + i];
    float s = 0.f;
    size_t base = (size_t)b*NCB*4096 + e;
    for (int c = 0; c < NCB; c++) {
        g_Sc[base + (size_t)c*4096] = s;
        s = p64*s + g_Mc[base + (size_t)c*4096];
    }
}

__global__ void bind_out()
{
    extern __shared__ float sm[];
    float* Qs  = sm;            // [64][65]  Q[t][l]
    float* KT  = sm + 4160;     // [64][64]  K^T[l][j] -> later Cq[t][i]
    float* SV  = sm + 8256;     // [64][64]  S^T[l][i] -> later V[j][i]
    float* As  = sm + 12352;    // [64][65]  A[t][j]
    float* pws = sm + 16512;    // [65][64]
    int b = blockIdx.x >> 5, c = blockIdx.x & 31;
    int tid = threadIdx.x;
    int t = tid >> 2, q0 = (tid & 3)*16;
    size_t zrow = ((size_t)(b*TT + c*CB + t))*N1;
    size_t srow = ((size_t)(b*NCB + c))*4096 + t*ODIM;
    #pragma unroll
    for (int u = 0; u < 4; u++) {
        float4 qv = *(const float4*)&g_Z[zrow + 640 + q0 + u*4];
        Qs[t*65 + q0+u*4+0] = qv.x; Qs[t*65 + q0+u*4+1] = qv.y;
        Qs[t*65 + q0+u*4+2] = qv.z; Qs[t*65 + q0+u*4+3] = qv.w;
        float4 kv = *(const float4*)&g_Z[zrow + 576 + q0 + u*4];     // t plays "j"
        KT[(q0+u*4+0)*ODIM + t] = kv.x; KT[(q0+u*4+1)*ODIM + t] = kv.y;
        KT[(q0+u*4+2)*ODIM + t] = kv.z; KT[(q0+u*4+3)*ODIM + t] = kv.w;
        float4 sv = *(const float4*)&g_Sc[srow + q0 + u*4];          // t plays "i"
        SV[(q0+u*4+0)*ODIM + t] = sv.x; SV[(q0+u*4+1)*ODIM + t] = sv.y;
        SV[(q0+u*4+2)*ODIM + t] = sv.z; SV[(q0+u*4+3)*ODIM + t] = sv.w;
    }
    for (int idx = tid; idx < 65*ODIM; idx += 256) pws[idx] = g_pw[idx];
    __syncthreads();

    float accA[16] = {}, accC[16] = {};
    for (int l = 0; l < ODIM; l++) {
        float q = Qs[t*65 + l];
        #pragma unroll
        for (int u = 0; u < 16; u += 4) {
            float4 k4 = *(const float4*)&KT[l*ODIM + q0 + u];
            float4 s4 = *(const float4*)&SV[l*ODIM + q0 + u];
            accA[u+0] += q*k4.x; accA[u+1] += q*k4.y; accA[u+2] += q*k4.z; accA[u+3] += q*k4.w;
            accC[u+0] += q*s4.x; accC[u+1] += q*s4.y; accC[u+2] += q*s4.z; accC[u+3] += q*s4.w;
        }
    }
    __syncthreads();
    #pragma unroll
    for (int u = 0; u < 16; u++) As[t*65 + q0 + u] = accA[u];
    #pragma unroll
    for (int u = 0; u < 16; u += 4)
        *(float4*)&KT[t*ODIM + q0 + u] = make_float4(accC[u], accC[u+1], accC[u+2], accC[u+3]);
    #pragma unroll
    for (int u = 0; u < 4; u++) {
        float4 vv = *(const float4*)&g_Z[zrow + 512 + q0 + u*4];     // t plays "j"
        *(float4*)&SV[t*ODIM + q0 + u*4] = vv;
    }
    __syncthreads();

    float o[16];
    #pragma unroll
    for (int u = 0; u < 16; u++)
        o[u] = pws[(t+1)*ODIM + q0 + u] * KT[t*ODIM + q0 + u];
    for (int j = 0; j <= t; j++) {
        float a = As[t*65 + j];
        int d = t - j;
        #pragma unroll
        for (int u = 0; u < 16; u += 4) {
            float4 p4 = *(const float4*)&pws[d*ODIM + q0 + u];
            float4 v4 = *(const float4*)&SV[j*ODIM + q0 + u];
            o[u+0] += a*p4.x*v4.x; o[u+1] += a*p4.y*v4.y;
            o[u+2] += a*p4.z*v4.z; o[u+3] += a*p4.w*v4.w;
        }
    }
    size_t orow = ((size_t)(b*TT + c*CB + t))*KC2 + SDIM + q0;
    #pragma unroll
    for (int u = 0; u < 16; u += 4)
        *(float4*)&g_A2[orow + u] = make_float4(tfr(o[u]), tfr(o[u+1]), tfr(o[u+2]), tfr(o[u+3]));
}

// ---------------- layernorm: warp per row ----------------
__global__ void ln_kernel(const float* __restrict__ lng, const float* __restrict__ lnb,
                          float* __restrict__ out)
{
    int row = blockIdx.x*8 + (threadIdx.x >> 5);
    int lane = threadIdx.x & 31;
    const float4* y4 = (const float4*)(g_Y + (size_t)row*DD);
    float4 v[4];
    float s = 0.f, s2 = 0.f;
    #pragma unroll
    for (int u = 0; u < 4; u++) {
        v[u] = y4[lane + u*32];
        s  += v[u].x + v[u].y + v[u].z + v[u].w;
        s2 += v[u].x*v[u].x + v[u].y*v[u].y + v[u].z*v[u].z + v[u].w*v[u].w;
    }
    #pragma unroll
    for (int off = 16; off; off >>= 1) {
        s  += __shfl_xor_sync(0xffffffffu, s,  off);
        s2 += __shfl_xor_sync(0xffffffffu, s2, off);
    }
    float mu  = s * (1.f/512.f);
    float var = s2 * (1.f/512.f) - mu*mu;
    float inv = rsqrtf(var + 1e-5f);
    float4* o4 = (float4*)(out + (size_t)row*DD);
    const float4* g4 = (const float4*)lng;
    const float4* b4 = (const float4*)lnb;
    #pragma unroll
    for (int u = 0; u < 4; u++) {
        float4 gg = g4[lane + u*32];
        float4 bb = b4[lane + u*32];
        float4 r;
        r.x = (v[u].x - mu)*inv*gg.x + bb.x;
        r.y = (v[u].y - mu)*inv*gg.y + bb.y;
        r.z = (v[u].z - mu)*inv*gg.z + bb.z;
        r.w = (v[u].w - mu)*inv*gg.w + bb.w;
        o4[lane + u*32] = r;
    }
}

// ---------------- host launch ----------------
extern "C" void kernel_launch(void* const* d_in, const int* in_sizes, int n_in,
                              void* d_out, int out_size)
{
    const float* x       = (const float*)d_in[0];
    const float* gate_W  = (const float*)d_in[1];
    const float* gate_b  = (const float*)d_in[2];
    const float* in_W    = (const float*)d_in[3];
    const float* in_b    = (const float*)d_in[4];
    const float* out_W   = (const float*)d_in[5];
    const float* out_b   = (const float*)d_in[6];
    const float* opv_W   = (const float*)d_in[7];
    const float* opv_b   = (const float*)d_in[8];
    const float* opk_W   = (const float*)d_in[9];
    const float* opk_b   = (const float*)d_in[10];
    const float* opq_W   = (const float*)d_in[11];
    const float* opq_b   = (const float*)d_in[12];
    const float* op_decay= (const float*)d_in[13];
    const float* opout_W = (const float*)d_in[14];
    const float* opout_b = (const float*)d_in[15];
    const float* ln_g    = (const float*)d_in[16];
    const float* ln_b    = (const float*)d_in[17];
    float* out = (float*)d_out;

    void *pW1, *pb1, *pZ, *pW2, *pb2, *pA2, *pY, *pXc;
    cudaGetSymbolAddress(&pW1, g_W1);
    cudaGetSymbolAddress(&pb1, g_b1);
    cudaGetSymbolAddress(&pZ,  g_Z);
    cudaGetSymbolAddress(&pW2, g_W2);
    cudaGetSymbolAddress(&pb2, g_b2);
    cudaGetSymbolAddress(&pA2, g_A2);
    cudaGetSymbolAddress(&pY,  g_Y);
    cudaGetSymbolAddress(&pXc, g_Xc);

    cudaFuncSetAttribute(bind_out, cudaFuncAttributeMaxDynamicSharedMemorySize, 20672*4);

    // prep
    pack_w1<<<(DD*N1 + 255)/256, 256>>>(gate_W, gate_b, in_W, in_b,
                                        opv_W, opv_b, opk_W, opk_b, opq_W, opq_b);
    pack_w2<<<(KC2*DD + 255)/256, 256>>>(out_W, out_b, opout_W, opout_b);
    pw_kernel<<<1, 64>>>(op_decay);
    cvt_x<<<(MM*DD/4)/256, 256>>>(x);

    // GEMM-1: Z = Xc @ W1 + b1
    gemm_tf32<<<dim3(N1/128, MM/128), 256>>>(
        (const float*)pXc, DD, (const float*)pW1, N1, (const float*)pb1,
        nullptr, 0, (float*)pZ, N1, DD);

    // gated scan
    scan_summ<<<BQ*NCH, SDIM>>>();
    scan_carry<<<BQ, SDIM>>>();
    scan_states<<<BQ*NCH, SDIM>>>();

    // binding scan
    bind_chunksum<<<BQ*NCB, 256>>>();
    bind_carry<<<BQ*NCB*16/32, 256>>>();
    bind_out<<<BQ*NCB, 256, 20672*4>>>();

    // GEMM-2: Y = A2 @ W2 + b2 + x
    gemm_tf32<<<dim3(DD/128, MM/128), 256>>>(
        (const float*)pA2, KC2, (const float*)pW2, DD, (const float*)pb2,
        x, DD, (float*)pY, DD, KC2);

    // layernorm -> out
    ln_kernel<<<MM/8, 256>>>(ln_g, ln_b, out);
}

// round 12
// speedup vs baseline: 1.2330x; 1.1059x over previous
#include <cuda_runtime.h>
#include <math.h>

// Problem constants
#define BQ 8
#define TT 2048
#define DD 512
#define SDIM 256
#define ODIM 64
#define MM (BQ*TT)          // 16384 rows
#define N1 768              // padded 704 (gate 0-255 | in 256-511 | v 512-575 | k 576-639 | q 640-703)
#define KC2 320             // states(256) + bind(64)
#define NCH 64              // scan chunks of 32
#define CHK 32
#define CB 64               // binding chunk
#define NCB 32

// ---------------- device scratch (no runtime allocation) ----------------
__device__ float g_W1[DD*N1];
__device__ float g_b1[N1];
__device__ float g_Z[(size_t)MM*N1];
__device__ float g_W2[KC2*DD];
__device__ float g_b2[DD];
__device__ float g_A2[(size_t)MM*KC2];    // written pre-rounded to tf32
__device__ float g_Y[(size_t)MM*DD];
__device__ float g_sumA[BQ*NCH*SDIM];
__device__ float g_sumB[BQ*NCH*SDIM];
__device__ float g_hpr[BQ*NCH*SDIM];
__device__ float g_Mc[(size_t)BQ*NCB*ODIM*ODIM];
__device__ float g_Sc[(size_t)BQ*NCB*ODIM*ODIM];
__device__ float g_pw[65*ODIM];

__device__ __forceinline__ float sigm_acc(float z){ return 1.0f/(1.0f+expf(-z)); }

__device__ __forceinline__ unsigned f2tf(float x){
    unsigned r; asm("cvt.rna.tf32.f32 %0, %1;" : "=r"(r) : "f"(x)); return r;
}
__device__ __forceinline__ float tfr(float x){ return __uint_as_float(f2tf(x)); }

// ---------------- prep kernels ----------------
__global__ void pack_w1(const float* __restrict__ gW, const float* __restrict__ gb,
                        const float* __restrict__ iW, const float* __restrict__ ib,
                        const float* __restrict__ vW, const float* __restrict__ vb,
                        const float* __restrict__ kW, const float* __restrict__ kb,
                        const float* __restrict__ qW, const float* __restrict__ qb)
{
    int idx = blockIdx.x*256 + threadIdx.x;
    if (idx < DD*N1) {
        int d = idx / N1, n = idx % N1;
        float w = 0.f;
        if      (n < 256) w = gW[d*256 + n];
        else if (n < 512) w = iW[d*256 + (n-256)];
        else if (n < 576) w = vW[d*64 + (n-512)];
        else if (n < 640) w = kW[d*64 + (n-576)];
        else if (n < 704) w = qW[d*64 + (n-640)];
        g_W1[idx] = tfr(w);
    }
    if (idx < N1) {
        float b = 0.f;
        if      (idx < 256) b = gb[idx];
        else if (idx < 512) b = ib[idx-256];
        else if (idx < 576) b = vb[idx-512];
        else if (idx < 640) b = kb[idx-576];
        else if (idx < 704) b = qb[idx-640];
        g_b1[idx] = b;
    }
}

__global__ void pack_w2(const float* __restrict__ oW, const float* __restrict__ ob,
                        const float* __restrict__ pW, const float* __restrict__ pb)
{
    int idx = blockIdx.x*256 + threadIdx.x;
    if (idx < KC2*DD) {
        int r = idx / DD, c = idx % DD;
        g_W2[idx] = tfr((r < 256) ? oW[r*DD + c] : pW[(r-256)*DD + c]);
    }
    if (idx < DD) g_b2[idx] = ob[idx] + pb[idx];
}

__global__ void pw_kernel(const float* __restrict__ op_decay)
{
    int i = threadIdx.x;
    if (i < ODIM) {
        float d = sigm_acc(op_decay[i]);
        float p = 1.f;
        for (int e = 0; e <= 64; e++) { g_pw[e*ODIM + i] = p; p *= d; }
    }
}

// ---------------- tf32 tensor-core GEMM (R4 proven config) ----------------
#define ASTRIDE 20
#define BSTRIDE 136

__device__ __forceinline__ void mma_tf32(float* c, const unsigned* a, const unsigned* b){
    asm volatile(
      "mma.sync.aligned.m16n8k8.row.col.f32.tf32.tf32.f32 "
      "{%0,%1,%2,%3}, {%4,%5,%6,%7}, {%8,%9}, {%0,%1,%2,%3};\n"
      : "+f"(c[0]), "+f"(c[1]), "+f"(c[2]), "+f"(c[3])
      : "r"(a[0]), "r"(a[1]), "r"(a[2]), "r"(a[3]), "r"(b[0]), "r"(b[1]));
}
__device__ __forceinline__ void cpa16(void* dst, const void* src){
    unsigned d = (unsigned)__cvta_generic_to_shared(dst);
    asm volatile("cp.async.cg.shared.global [%0], [%1], 16;" :: "r"(d), "l"(src));
}

__global__ void __launch_bounds__(256,2) gemm_tf32(
    const float* __restrict__ A, int lda,
    const float* __restrict__ Bw, int ldb,
    const float* __restrict__ bias,
    const float* __restrict__ addsrc, int ldadd,
    float* __restrict__ C, int ldc, int K)
{
    __shared__ float As[2][128][ASTRIDE];   // [m][k] padded
    __shared__ float Bs[2][16][BSTRIDE];    // [k][n] padded

    int tid  = threadIdx.x;
    int lane = tid & 31, warp = tid >> 5;
    int wm = (warp >> 2) * 64;
    int wn = (warp & 3) * 32;
    int lr = lane >> 2;
    int lc = lane & 3;

    size_t rowBase = (size_t)blockIdx.y * 128;
    int colBase = blockIdx.x * 128;

    int ac0 = tid, ac1 = tid + 256;

    float acc[4][4][4];
    #pragma unroll
    for (int i = 0; i < 4; i++)
        #pragma unroll
        for (int j = 0; j < 4; j++)
            #pragma unroll
            for (int u = 0; u < 4; u++) acc[i][j][u] = 0.f;

    int nIter = K / 16;

    {
        int r0 = ac0 >> 2, kc0 = (ac0 & 3) * 4;
        int r1 = ac1 >> 2, kc1 = (ac1 & 3) * 4;
        cpa16(&As[0][r0][kc0], A + (rowBase + r0)*lda + kc0);
        cpa16(&As[0][r1][kc1], A + (rowBase + r1)*lda + kc1);
        int br0 = ac0 >> 5, bn0 = (ac0 & 31) * 4;
        int br1 = ac1 >> 5, bn1 = (ac1 & 31) * 4;
        cpa16(&Bs[0][br0][bn0], Bw + (size_t)br0*ldb + colBase + bn0);
        cpa16(&Bs[0][br1][bn1], Bw + (size_t)br1*ldb + colBase + bn1);
        asm volatile("cp.async.commit_group;");
    }

    int buf = 0;
    for (int it = 0; it < nIter; it++) {
        asm volatile("cp.async.wait_group 0;");
        __syncthreads();

        if (it + 1 < nIter) {
            int k0 = (it + 1) * 16;
            int nb = buf ^ 1;
            int r0 = ac0 >> 2, kc0 = (ac0 & 3) * 4;
            int r1 = ac1 >> 2, kc1 = (ac1 & 3) * 4;
            cpa16(&As[nb][r0][kc0], A + (rowBase + r0)*lda + k0 + kc0);
            cpa16(&As[nb][r1][kc1], A + (rowBase + r1)*lda + k0 + kc1);
            int br0 = ac0 >> 5, bn0 = (ac0 & 31) * 4;
            int br1 = ac1 >> 5, bn1 = (ac1 & 31) * 4;
            cpa16(&Bs[nb][br0][bn0], Bw + (size_t)(k0+br0)*ldb + colBase + bn0);
            cpa16(&Bs[nb][br1][bn1], Bw + (size_t)(k0+br1)*ldb + colBase + bn1);
            asm volatile("cp.async.commit_group;");
        }

        #pragma unroll
        for (int kk = 0; kk < 16; kk += 8) {
            unsigned af[4][4], bf[4][2];
            #pragma unroll
            for (int mt = 0; mt < 4; mt++) {
                int m0 = wm + mt*16 + lr;
                af[mt][0] = __float_as_uint(As[buf][m0    ][kk + lc]);
                af[mt][1] = __float_as_uint(As[buf][m0 + 8][kk + lc]);
                af[mt][2] = __float_as_uint(As[buf][m0    ][kk + lc + 4]);
                af[mt][3] = __float_as_uint(As[buf][m0 + 8][kk + lc + 4]);
            }
            #pragma unroll
            for (int nt = 0; nt < 4; nt++) {
                int n0 = wn + nt*8 + lr;
                bf[nt][0] = __float_as_uint(Bs[buf][kk + lc    ][n0]);
                bf[nt][1] = __float_as_uint(Bs[buf][kk + lc + 4][n0]);
            }
            #pragma unroll
            for (int mt = 0; mt < 4; mt++)
                #pragma unroll
                for (int nt = 0; nt < 4; nt++)
                    mma_tf32(acc[mt][nt], af[mt], bf[nt]);
        }
        buf ^= 1;
    }

    // epilogue
    #pragma unroll
    for (int mt = 0; mt < 4; mt++) {
        size_t row0 = rowBase + wm + mt*16 + lr;
        #pragma unroll
        for (int nt = 0; nt < 4; nt++) {
            int col = colBase + wn + nt*8 + lc*2;
            float b0 = bias[col], b1 = bias[col+1];
            float a00=0.f,a01=0.f,a10=0.f,a11=0.f;
            if (addsrc) {
                const float* p0 = addsrc + row0*(size_t)ldadd + col;
                const float* p1 = addsrc + (row0+8)*(size_t)ldadd + col;
                a00 = p0[0]; a01 = p0[1]; a10 = p1[0]; a11 = p1[1];
            }
            float2 r0 = make_float2(acc[mt][nt][0] + b0 + a00, acc[mt][nt][1] + b1 + a01);
            float2 r1 = make_float2(acc[mt][nt][2] + b0 + a10, acc[mt][nt][3] + b1 + a11);
            *(float2*)(C + row0*(size_t)ldc + col)     = r0;
            *(float2*)(C + (row0+8)*(size_t)ldc + col) = r1;
        }
    }
}

// ---------------- gated scan (reciprocal-product formulation) ----------------
__device__ __forceinline__ void scan_step(float zg, float zi, float& rca, float& wb)
{
    float t = __expf(-zg);
    float rca_new = rca * (1.f + t);
    float c = zi * t * rca;
    if (rca_new > 1e8f) c = zi * t * rca * __fdividef(1e8f, rca_new);
    wb += c;
    rca = rca_new;
}

__global__ void scan_summ()
{
    int bc = blockIdx.x;               // 0..511
    int b = bc >> 6, c = bc & 63;
    int sd = threadIdx.x;
    const float* zp = g_Z + ((size_t)(b*TT + c*CHK))*N1 + sd;
    float rca = 1.f, wb = 0.f;
    #pragma unroll 8
    for (int k = 0; k < CHK; k++) {
        float zg = zp[0];
        float zi = zp[SDIM];
        scan_step(zg, zi, rca, wb);
        zp += N1;
    }
    int idx = bc*SDIM + sd;
    g_sumA[idx] = __fdividef(1.f, rca);
    g_sumB[idx] = wb;
}

__global__ void scan_carry()
{
    int b = blockIdx.x;
    int sd = threadIdx.x;
    float h = 0.f;
    #pragma unroll 8
    for (int c = 0; c < NCH; c++) {
        int idx = (b*NCH + c)*SDIM + sd;
        g_hpr[idx] = h;
        h = g_sumA[idx]*(h + g_sumB[idx]);
    }
}

__global__ void scan_states()
{
    int bc = blockIdx.x;
    int b = bc >> 6, c = bc & 63;
    int sd = threadIdx.x;
    const float* zp = g_Z + ((size_t)(b*TT + c*CHK))*N1 + sd;
    float* op = g_A2 + ((size_t)(b*TT + c*CHK))*KC2 + sd;
    float h = g_hpr[bc*SDIM + sd];
    float rca = 1.f, wb = 0.f;
    #pragma unroll 4
    for (int k = 0; k < CHK; k++) {
        float zg = zp[0];
        float zi = zp[SDIM];
        scan_step(zg, zi, rca, wb);
        *op = tfr(__fdividef(h + wb, rca));
        zp += N1; op += KC2;
    }
}

// ---------------- binding scan ----------------
// M[i][l] = sum_j dec_i^(63-j) v_j[i] k_j[l]. 2x i-register-blocked compute.
__global__ void bind_chunksum()
{
    __shared__ float Vs[CB*ODIM];
    __shared__ float Ks[CB*ODIM];
    int b = blockIdx.x >> 5, c = blockIdx.x & 31;
    int tid = threadIdx.x;
    int j = tid >> 2, q0 = (tid & 3)*16;
    size_t zrow = ((size_t)(b*TT + c*CB + j))*N1;
    #pragma unroll
    for (int u = 0; u < 4; u++) {
        float4 vv = *(const float4*)&g_Z[zrow + 512 + q0 + u*4];
        float4 pp = *(const float4*)&g_pw[(63-j)*ODIM + q0 + u*4];
        vv.x *= pp.x; vv.y *= pp.y; vv.z *= pp.z; vv.w *= pp.w;
        *(float4*)&Vs[j*ODIM + q0 + u*4] = vv;
        float4 kk = *(const float4*)&g_Z[zrow + 576 + q0 + u*4];
        *(float4*)&Ks[j*ODIM + q0 + u*4] = kk;
    }
    __syncthreads();
    if (tid < 128) {
        int i = tid >> 2;               // 0..31  (also handles i+32)
        int l0 = (tid & 3)*16;
        float acc0[16] = {}, acc1[16] = {};
        for (int jj = 0; jj < CB; jj++) {
            float v0 = Vs[jj*ODIM + i];
            float v1 = Vs[jj*ODIM + i + 32];
            #pragma unroll
            for (int u = 0; u < 16; u += 4) {
                float4 k4 = *(const float4*)&Ks[jj*ODIM + l0 + u];
                acc0[u+0] += v0*k4.x; acc0[u+1] += v0*k4.y;
                acc0[u+2] += v0*k4.z; acc0[u+3] += v0*k4.w;
                acc1[u+0] += v1*k4.x; acc1[u+1] += v1*k4.y;
                acc1[u+2] += v1*k4.z; acc1[u+3] += v1*k4.w;
            }
        }
        size_t mb0 = ((size_t)(b*NCB + c))*ODIM*ODIM + i*ODIM + l0;
        size_t mb1 = mb0 + 32*ODIM;
        #pragma unroll
        for (int u = 0; u < 16; u += 4) {
            *(float4*)&g_Mc[mb0 + u] = make_float4(acc0[u], acc0[u+1], acc0[u+2], acc0[u+3]);
            *(float4*)&g_Mc[mb1 + u] = make_float4(acc1[u], acc1[u+1], acc1[u+2], acc1[u+3]);
        }
    }
}

__global__ void bind_carry()
{
    int gid = blockIdx.x*blockDim.x + threadIdx.x;   // 32768 lanes
    int b = gid >> 12, e = gid & 4095, i = e >> 6;
    float p64 = g_pw[64*ODIM + i];
    float s = 0.f;
    #pragma unroll 8
    for (int c = 0; c < NCB; c++) {
        size_t a = (size_t)b*NCB*4096 + (size_t)c*4096 + e;
        g_Sc[a] = s;
        s = p64*s + g_Mc[a];
    }
}

// 2x t-register-blocked bind_out
__global__ void bind_out()
{
    extern __shared__ float sm[];
    float* Qs  = sm;            // [64][65]  Q[t][l]
    float* KT  = sm + 4160;     // [64][64]  K^T[l][j] -> later Cq[t][i]
    float* SV  = sm + 8256;     // [64][64]  S^T[l][i] -> later V[j][i]
    float* As  = sm + 12352;    // [64][65]  A[t][j]
    float* pws = sm + 16512;    // [65][64]
    int b = blockIdx.x >> 5, c = blockIdx.x & 31;
    int tid = threadIdx.x;
    int t = tid >> 2, q0 = (tid & 3)*16;
    size_t zrow = ((size_t)(b*TT + c*CB + t))*N1;
    size_t srow = ((size_t)(b*NCB + c))*4096 + t*ODIM;
    // phase 0: load Q, K^T, S^T, pw (full 256-thread mapping)
    #pragma unroll
    for (int u = 0; u < 4; u++) {
        float4 qv = *(const float4*)&g_Z[zrow + 640 + q0 + u*4];
        Qs[t*65 + q0+u*4+0] = qv.x; Qs[t*65 + q0+u*4+1] = qv.y;
        Qs[t*65 + q0+u*4+2] = qv.z; Qs[t*65 + q0+u*4+3] = qv.w;
        float4 kv = *(const float4*)&g_Z[zrow + 576 + q0 + u*4];     // t plays "j"
        KT[(q0+u*4+0)*ODIM + t] = kv.x; KT[(q0+u*4+1)*ODIM + t] = kv.y;
        KT[(q0+u*4+2)*ODIM + t] = kv.z; KT[(q0+u*4+3)*ODIM + t] = kv.w;
        float4 sv = *(const float4*)&g_Sc[srow + q0 + u*4];          // t plays "i"
        SV[(q0+u*4+0)*ODIM + t] = sv.x; SV[(q0+u*4+1)*ODIM + t] = sv.y;
        SV[(q0+u*4+2)*ODIM + t] = sv.z; SV[(q0+u*4+3)*ODIM + t] = sv.w;
    }
    for (int idx = tid; idx < 65*ODIM; idx += 256) pws[idx] = g_pw[idx];
    __syncthreads();

    // phase 1: A = Q K^T, Cq = Q S^T   (128 threads, t0 and t0+32 each)
    int t0 = (tid >> 2) & 31;
    float accA0[16], accA1[16], accC0[16], accC1[16];
    if (tid < 128) {
        #pragma unroll
        for (int u = 0; u < 16; u++) { accA0[u]=0.f; accA1[u]=0.f; accC0[u]=0.f; accC1[u]=0.f; }
        for (int l = 0; l < ODIM; l++) {
            float qa = Qs[t0*65 + l];
            float qb = Qs[(t0+32)*65 + l];
            #pragma unroll
            for (int u = 0; u < 16; u += 4) {
                float4 k4 = *(const float4*)&KT[l*ODIM + q0 + u];
                float4 s4 = *(const float4*)&SV[l*ODIM + q0 + u];
                accA0[u+0] += qa*k4.x; accA0[u+1] += qa*k4.y; accA0[u+2] += qa*k4.z; accA0[u+3] += qa*k4.w;
                accA1[u+0] += qb*k4.x; accA1[u+1] += qb*k4.y; accA1[u+2] += qb*k4.z; accA1[u+3] += qb*k4.w;
                accC0[u+0] += qa*s4.x; accC0[u+1] += qa*s4.y; accC0[u+2] += qa*s4.z; accC0[u+3] += qa*s4.w;
                accC1[u+0] += qb*s4.x; accC1[u+1] += qb*s4.y; accC1[u+2] += qb*s4.z; accC1[u+3] += qb*s4.w;
            }
        }
    }
    __syncthreads();
    // phase 2: write As and Cq (overwrite KT); reload V into SV (256-thread mapping)
    if (tid < 128) {
        #pragma unroll
        for (int u = 0; u < 16; u++) {
            As[t0*65 + q0 + u]      = accA0[u];
            As[(t0+32)*65 + q0 + u] = accA1[u];
        }
        #pragma unroll
        for (int u = 0; u < 16; u += 4) {
            *(float4*)&KT[t0*ODIM + q0 + u]      = make_float4(accC0[u], accC0[u+1], accC0[u+2], accC0[u+3]);
            *(float4*)&KT[(t0+32)*ODIM + q0 + u] = make_float4(accC1[u], accC1[u+1], accC1[u+2], accC1[u+3]);
        }
    }
    #pragma unroll
    for (int u = 0; u < 4; u++) {
        float4 vv = *(const float4*)&g_Z[zrow + 512 + q0 + u*4];     // t plays "j"
        *(float4*)&SV[t*ODIM + q0 + u*4] = vv;
    }
    __syncthreads();

    // phase 3: o_t = dec^(t+1)*Cq + sum_{j<=t} A[t][j] dec^(t-j) v_j   (128 threads, 2 t's)
    if (tid < 128) {
        int ta = t0, tb = t0 + 32;
        float o0[16], o1[16];
        #pragma unroll
        for (int u = 0; u < 16; u++) {
            o0[u] = pws[(ta+1)*ODIM + q0 + u] * KT[ta*ODIM + q0 + u];
            o1[u] = pws[(tb+1)*ODIM + q0 + u] * KT[tb*ODIM + q0 + u];
        }
        for (int j = 0; j <= tb; j++) {
            float a1 = As[tb*65 + j];
            int d1 = tb - j;
            bool inA = (j <= ta);
            float a0 = inA ? As[ta*65 + j] : 0.f;
            int d0 = inA ? (ta - j) : 0;
            #pragma unroll
            for (int u = 0; u < 16; u += 4) {
                float4 v4  = *(const float4*)&SV[j*ODIM + q0 + u];
                float4 p1v = *(const float4*)&pws[d1*ODIM + q0 + u];
                o1[u+0] += a1*p1v.x*v4.x; o1[u+1] += a1*p1v.y*v4.y;
                o1[u+2] += a1*p1v.z*v4.z; o1[u+3] += a1*p1v.w*v4.w;
                if (inA) {
                    float4 p0v = *(const float4*)&pws[d0*ODIM + q0 + u];
                    o0[u+0] += a0*p0v.x*v4.x; o0[u+1] += a0*p0v.y*v4.y;
                    o0[u+2] += a0*p0v.z*v4.z; o0[u+3] += a0*p0v.w*v4.w;
                }
            }
        }
        size_t orow0 = ((size_t)(b*TT + c*CB + ta))*KC2 + SDIM + q0;
        size_t orow1 = ((size_t)(b*TT + c*CB + tb))*KC2 + SDIM + q0;
        #pragma unroll
        for (int u = 0; u < 16; u += 4) {
            *(float4*)&g_A2[orow0 + u] = make_float4(tfr(o0[u]), tfr(o0[u+1]), tfr(o0[u+2]), tfr(o0[u+3]));
            *(float4*)&g_A2[orow1 + u] = make_float4(tfr(o1[u]), tfr(o1[u+1]), tfr(o1[u+2]), tfr(o1[u+3]));
        }
    }
}

// ---------------- layernorm: warp per row ----------------
__global__ void ln_kernel(const float* __restrict__ lng, const float* __restrict__ lnb,
                          float* __restrict__ out)
{
    int row = blockIdx.x*8 + (threadIdx.x >> 5);
    int lane = threadIdx.x & 31;
    const float4* y4 = (const float4*)(g_Y + (size_t)row*DD);
    float4 v[4];
    float s = 0.f, s2 = 0.f;
    #pragma unroll
    for (int u = 0; u < 4; u++) {
        v[u] = y4[lane + u*32];
        s  += v[u].x + v[u].y + v[u].z + v[u].w;
        s2 += v[u].x*v[u].x + v[u].y*v[u].y + v[u].z*v[u].z + v[u].w*v[u].w;
    }
    #pragma unroll
    for (int off = 16; off; off >>= 1) {
        s  += __shfl_xor_sync(0xffffffffu, s,  off);
        s2 += __shfl_xor_sync(0xffffffffu, s2, off);
    }
    float mu  = s * (1.f/512.f);
    float var = s2 * (1.f/512.f) - mu*mu;
    float inv = rsqrtf(var + 1e-5f);
    float4* o4 = (float4*)(out + (size_t)row*DD);
    const float4* g4 = (const float4*)lng;
    const float4* b4 = (const float4*)lnb;
    #pragma unroll
    for (int u = 0; u < 4; u++) {
        float4 gg = g4[lane + u*32];
        float4 bb = b4[lane + u*32];
        float4 r;
        r.x = (v[u].x - mu)*inv*gg.x + bb.x;
        r.y = (v[u].y - mu)*inv*gg.y + bb.y;
        r.z = (v[u].z - mu)*inv*gg.z + bb.z;
        r.w = (v[u].w - mu)*inv*gg.w + bb.w;
        o4[lane + u*32] = r;
    }
}

// ---------------- host launch ----------------
extern "C" void kernel_launch(void* const* d_in, const int* in_sizes, int n_in,
                              void* d_out, int out_size)
{
    const float* x       = (const float*)d_in[0];
    const float* gate_W  = (const float*)d_in[1];
    const float* gate_b  = (const float*)d_in[2];
    const float* in_W    = (const float*)d_in[3];
    const float* in_b    = (const float*)d_in[4];
    const float* out_W   = (const float*)d_in[5];
    const float* out_b   = (const float*)d_in[6];
    const float* opv_W   = (const float*)d_in[7];
    const float* opv_b   = (const float*)d_in[8];
    const float* opk_W   = (const float*)d_in[9];
    const float* opk_b   = (const float*)d_in[10];
    const float* opq_W   = (const float*)d_in[11];
    const float* opq_b   = (const float*)d_in[12];
    const float* op_decay= (const float*)d_in[13];
    const float* opout_W = (const float*)d_in[14];
    const float* opout_b = (const float*)d_in[15];
    const float* ln_g    = (const float*)d_in[16];
    const float* ln_b    = (const float*)d_in[17];
    float* out = (float*)d_out;

    void *pW1, *pb1, *pZ, *pW2, *pb2, *pA2, *pY;
    cudaGetSymbolAddress(&pW1, g_W1);
    cudaGetSymbolAddress(&pb1, g_b1);
    cudaGetSymbolAddress(&pZ,  g_Z);
    cudaGetSymbolAddress(&pW2, g_W2);
    cudaGetSymbolAddress(&pb2, g_b2);
    cudaGetSymbolAddress(&pA2, g_A2);
    cudaGetSymbolAddress(&pY,  g_Y);

    cudaFuncSetAttribute(bind_out, cudaFuncAttributeMaxDynamicSharedMemorySize, 20672*4);

    // prep
    pack_w1<<<(DD*N1 + 255)/256, 256>>>(gate_W, gate_b, in_W, in_b,
                                        opv_W, opv_b, opk_W, opk_b, opq_W, opq_b);
    pack_w2<<<(KC2*DD + 255)/256, 256>>>(out_W, out_b, opout_W, opout_b);
    pw_kernel<<<1, 64>>>(op_decay);

    // GEMM-1: Z = x @ W1 + b1  (A consumed raw; tf32 HW truncation on A operand)
    gemm_tf32<<<dim3(N1/128, MM/128), 256>>>(
        x, DD, (const float*)pW1, N1, (const float*)pb1,
        nullptr, 0, (float*)pZ, N1, DD);

    // gated scan
    scan_summ<<<BQ*NCH, SDIM>>>();
    scan_carry<<<BQ, SDIM>>>();
    scan_states<<<BQ*NCH, SDIM>>>();

    // binding scan
    bind_chunksum<<<BQ*NCB, 256>>>();
    bind_carry<<<BQ*NCB*16/32, 256>>>();
    bind_out<<<BQ*NCB, 256, 20672*4>>>();

    // GEMM-2: Y = A2 @ W2 + b2 + x
    gemm_tf32<<<dim3(DD/128, MM/128), 256>>>(
        (const float*)pA2, KC2, (const float*)pW2, DD, (const float*)pb2,
        x, DD, (float*)pY, DD, KC2);

    // layernorm -> out
    ln_kernel<<<MM/8, 256>>>(ln_g, ln_b, out);
}

// round 13
// speedup vs baseline: 1.3018x; 1.0558x over previous
#include <cuda_runtime.h>
#include <math.h>

// Problem constants
#define BQ 8
#define TT 2048
#define DD 512
#define SDIM 256
#define ODIM 64
#define MM (BQ*TT)          // 16384 rows
#define N1 768              // padded 704 (gate 0-255 | in 256-511 | v 512-575 | k 576-639 | q 640-703)
#define KC2 320             // states(256) + bind(64)
#define NCH 64              // scan chunks of 32
#define CHK 32
#define CB 64               // binding chunk
#define NCB 32

// ---------------- device scratch (no runtime allocation) ----------------
__device__ float g_W1[DD*N1];
__device__ float g_b1[N1];
__device__ float g_Z[(size_t)MM*N1];
__device__ float g_W2[KC2*DD];
__device__ float g_b2[DD];
__device__ float g_A2[(size_t)MM*KC2];    // written pre-rounded to tf32
__device__ float g_Y[(size_t)MM*DD];
__device__ float g_sumA[BQ*NCH*SDIM];
__device__ float g_sumB[BQ*NCH*SDIM];
__device__ float g_hpr[BQ*NCH*SDIM];
__device__ float g_Mc[(size_t)BQ*NCB*ODIM*ODIM];
__device__ float g_Sc[(size_t)BQ*NCB*ODIM*ODIM];
__device__ float g_pw[65*ODIM];

__device__ __forceinline__ float sigm_acc(float z){ return 1.0f/(1.0f+expf(-z)); }

__device__ __forceinline__ unsigned f2tf(float x){
    unsigned r; asm("cvt.rna.tf32.f32 %0, %1;" : "=r"(r) : "f"(x)); return r;
}
__device__ __forceinline__ float tfr(float x){ return __uint_as_float(f2tf(x)); }

// ---------------- fused prep kernel ----------------
// blocks [0,1536): W1; [1536,2176): W2; 2176: pw
__global__ void pack_all(const float* __restrict__ gW, const float* __restrict__ gb,
                         const float* __restrict__ iW, const float* __restrict__ ib,
                         const float* __restrict__ vW, const float* __restrict__ vb,
                         const float* __restrict__ kW, const float* __restrict__ kb,
                         const float* __restrict__ qW, const float* __restrict__ qb,
                         const float* __restrict__ oW, const float* __restrict__ ob,
                         const float* __restrict__ pW, const float* __restrict__ pb,
                         const float* __restrict__ op_decay)
{
    int bid = blockIdx.x;
    if (bid < 1536) {
        int idx = bid*256 + threadIdx.x;
        int d = idx / N1, n = idx % N1;
        float w = 0.f;
        if      (n < 256) w = gW[d*256 + n];
        else if (n < 512) w = iW[d*256 + (n-256)];
        else if (n < 576) w = vW[d*64 + (n-512)];
        else if (n < 640) w = kW[d*64 + (n-576)];
        else if (n < 704) w = qW[d*64 + (n-640)];
        g_W1[idx] = tfr(w);
        if (idx < N1) {
            float b = 0.f;
            if      (idx < 256) b = gb[idx];
            else if (idx < 512) b = ib[idx-256];
            else if (idx < 576) b = vb[idx-512];
            else if (idx < 640) b = kb[idx-576];
            else if (idx < 704) b = qb[idx-640];
            g_b1[idx] = b;
        }
    } else if (bid < 2176) {
        int idx = (bid-1536)*256 + threadIdx.x;
        int r = idx / DD, c = idx % DD;
        g_W2[idx] = tfr((r < 256) ? oW[r*DD + c] : pW[(r-256)*DD + c]);
        if (idx < DD) g_b2[idx] = ob[idx] + pb[idx];
    } else {
        int i = threadIdx.x;
        if (i < ODIM) {
            float d = sigm_acc(op_decay[i]);
            float p = 1.f;
            for (int e = 0; e <= 64; e++) { g_pw[e*ODIM + i] = p; p *= d; }
        }
    }
}

// ---------------- tf32 tensor-core GEMM, BK=32 ----------------
#define AST2 36
#define BSTR 136
#define A_BUF_F (128*AST2)          // 4608 floats per buffer
#define B_BUF_F (32*BSTR)           // 4352 floats per buffer
#define GEMM_SMEM ((2*A_BUF_F + 2*B_BUF_F)*4)   // 71680 bytes

__device__ __forceinline__ void mma_tf32(float* c, const unsigned* a, const unsigned* b){
    asm volatile(
      "mma.sync.aligned.m16n8k8.row.col.f32.tf32.tf32.f32 "
      "{%0,%1,%2,%3}, {%4,%5,%6,%7}, {%8,%9}, {%0,%1,%2,%3};\n"
      : "+f"(c[0]), "+f"(c[1]), "+f"(c[2]), "+f"(c[3])
      : "r"(a[0]), "r"(a[1]), "r"(a[2]), "r"(a[3]), "r"(b[0]), "r"(b[1]));
}
__device__ __forceinline__ void cpa16(void* dst, const void* src){
    unsigned d = (unsigned)__cvta_generic_to_shared(dst);
    asm volatile("cp.async.cg.shared.global [%0], [%1], 16;" :: "r"(d), "l"(src));
}

__global__ void __launch_bounds__(256,2) gemm_tf32(
    const float* __restrict__ A, int lda,
    const float* __restrict__ Bw, int ldb,
    const float* __restrict__ bias,
    const float* __restrict__ addsrc, int ldadd,
    float* __restrict__ C, int ldc, int K)
{
    extern __shared__ float sm[];
    // layout: As[2][128][36] | Bs[2][32][136]

    int tid  = threadIdx.x;
    int lane = tid & 31, warp = tid >> 5;
    int wm = (warp >> 2) * 64;
    int wn = (warp & 3) * 32;
    int lr = lane >> 2;
    int lc = lane & 3;

    size_t rowBase = (size_t)blockIdx.y * 128;
    int colBase = blockIdx.x * 128;

    // per-tile: 1024 A-chunks + 1024 B-chunks, 4 of each per thread
    int ar[4], akc[4], bbr[4], bbn[4];
    #pragma unroll
    for (int j = 0; j < 4; j++) {
        int ac = tid + j*256;
        ar[j]  = ac >> 3;  akc[j] = (ac & 7) * 4;
        bbr[j] = ac >> 5;  bbn[j] = (ac & 31) * 4;
    }

    float acc[4][4][4];
    #pragma unroll
    for (int i = 0; i < 4; i++)
        #pragma unroll
        for (int j = 0; j < 4; j++)
            #pragma unroll
            for (int u = 0; u < 4; u++) acc[i][j][u] = 0.f;

    int nIter = K / 32;

    // prologue: tile 0 -> buf 0
    {
        float* Asb = sm;
        float* Bsb = sm + 2*A_BUF_F;
        #pragma unroll
        for (int j = 0; j < 4; j++) {
            cpa16(Asb + ar[j]*AST2 + akc[j], A + (rowBase + ar[j])*lda + akc[j]);
            cpa16(Bsb + bbr[j]*BSTR + bbn[j], Bw + (size_t)bbr[j]*ldb + colBase + bbn[j]);
        }
        asm volatile("cp.async.commit_group;");
    }

    int buf = 0;
    for (int it = 0; it < nIter; it++) {
        asm volatile("cp.async.wait_group 0;");
        __syncthreads();

        if (it + 1 < nIter) {
            int k0 = (it + 1) * 32;
            int nb = buf ^ 1;
            float* Asb = sm + nb*A_BUF_F;
            float* Bsb = sm + 2*A_BUF_F + nb*B_BUF_F;
            #pragma unroll
            for (int j = 0; j < 4; j++) {
                cpa16(Asb + ar[j]*AST2 + akc[j], A + (rowBase + ar[j])*lda + k0 + akc[j]);
                cpa16(Bsb + bbr[j]*BSTR + bbn[j], Bw + (size_t)(k0+bbr[j])*ldb + colBase + bbn[j]);
            }
            asm volatile("cp.async.commit_group;");
        }

        const float* Asb = sm + buf*A_BUF_F;
        const float* Bsb = sm + 2*A_BUF_F + buf*B_BUF_F;

        #pragma unroll
        for (int kk = 0; kk < 32; kk += 8) {
            unsigned af[4][4], bf[4][2];
            #pragma unroll
            for (int mt = 0; mt < 4; mt++) {
                int m0 = wm + mt*16 + lr;
                af[mt][0] = __float_as_uint(Asb[m0*AST2 + kk + lc]);
                af[mt][1] = __float_as_uint(Asb[(m0+8)*AST2 + kk + lc]);
                af[mt][2] = __float_as_uint(Asb[m0*AST2 + kk + lc + 4]);
                af[mt][3] = __float_as_uint(Asb[(m0+8)*AST2 + kk + lc + 4]);
            }
            #pragma unroll
            for (int nt = 0; nt < 4; nt++) {
                int n0 = wn + nt*8 + lr;
                bf[nt][0] = __float_as_uint(Bsb[(kk + lc)*BSTR + n0]);
                bf[nt][1] = __float_as_uint(Bsb[(kk + lc + 4)*BSTR + n0]);
            }
            #pragma unroll
            for (int mt = 0; mt < 4; mt++)
                #pragma unroll
                for (int nt = 0; nt < 4; nt++)
                    mma_tf32(acc[mt][nt], af[mt], bf[nt]);
        }
        buf ^= 1;
    }

    // epilogue
    #pragma unroll
    for (int mt = 0; mt < 4; mt++) {
        size_t row0 = rowBase + wm + mt*16 + lr;
        #pragma unroll
        for (int nt = 0; nt < 4; nt++) {
            int col = colBase + wn + nt*8 + lc*2;
            float b0 = bias[col], b1 = bias[col+1];
            float a00=0.f,a01=0.f,a10=0.f,a11=0.f;
            if (addsrc) {
                const float* p0 = addsrc + row0*(size_t)ldadd + col;
                const float* p1 = addsrc + (row0+8)*(size_t)ldadd + col;
                a00 = p0[0]; a01 = p0[1]; a10 = p1[0]; a11 = p1[1];
            }
            float2 r0 = make_float2(acc[mt][nt][0] + b0 + a00, acc[mt][nt][1] + b1 + a01);
            float2 r1 = make_float2(acc[mt][nt][2] + b0 + a10, acc[mt][nt][3] + b1 + a11);
            *(float2*)(C + row0*(size_t)ldc + col)     = r0;
            *(float2*)(C + (row0+8)*(size_t)ldc + col) = r1;
        }
    }
}

// ---------------- gated scan helpers ----------------
__device__ __forceinline__ void scan_step(float zg, float zi, float& rca, float& wb)
{
    float t = __expf(-zg);
    float rca_new = rca * (1.f + t);
    float c = zi * t * rca;
    if (rca_new > 1e8f) c = zi * t * rca * __fdividef(1e8f, rca_new);
    wb += c;
    rca = rca_new;
}

// ---------------- fused phase 1: scan_summ (blocks 0..511) | bind_chunksum (512..767) ----------------
__global__ void __launch_bounds__(256) phase1()
{
    __shared__ float Vs[CB*ODIM];
    __shared__ float Ks[CB*ODIM];
    int bid = blockIdx.x;
    int tid = threadIdx.x;
    if (bid < 512) {
        // scan_summ
        int b = bid >> 6, c = bid & 63;
        int sd = tid;
        const float* zp = g_Z + ((size_t)(b*TT + c*CHK))*N1 + sd;
        float rca = 1.f, wb = 0.f;
        #pragma unroll 8
        for (int k = 0; k < CHK; k++) {
            float zg = zp[0];
            float zi = zp[SDIM];
            scan_step(zg, zi, rca, wb);
            zp += N1;
        }
        int idx = bid*SDIM + sd;
        g_sumA[idx] = __fdividef(1.f, rca);
        g_sumB[idx] = wb;
    } else {
        // bind_chunksum
        int bc = bid - 512;
        int b = bc >> 5, c = bc & 31;
        int j = tid >> 2, q0 = (tid & 3)*16;
        size_t zrow = ((size_t)(b*TT + c*CB + j))*N1;
        #pragma unroll
        for (int u = 0; u < 4; u++) {
            float4 vv = *(const float4*)&g_Z[zrow + 512 + q0 + u*4];
            float4 pp = *(const float4*)&g_pw[(63-j)*ODIM + q0 + u*4];
            vv.x *= pp.x; vv.y *= pp.y; vv.z *= pp.z; vv.w *= pp.w;
            *(float4*)&Vs[j*ODIM + q0 + u*4] = vv;
            float4 kk = *(const float4*)&g_Z[zrow + 576 + q0 + u*4];
            *(float4*)&Ks[j*ODIM + q0 + u*4] = kk;
        }
        __syncthreads();
        if (tid < 128) {
            int i = tid >> 2;
            int l0 = (tid & 3)*16;
            float acc0[16] = {}, acc1[16] = {};
            for (int jj = 0; jj < CB; jj++) {
                float v0 = Vs[jj*ODIM + i];
                float v1 = Vs[jj*ODIM + i + 32];
                #pragma unroll
                for (int u = 0; u < 16; u += 4) {
                    float4 k4 = *(const float4*)&Ks[jj*ODIM + l0 + u];
                    acc0[u+0] += v0*k4.x; acc0[u+1] += v0*k4.y;
                    acc0[u+2] += v0*k4.z; acc0[u+3] += v0*k4.w;
                    acc1[u+0] += v1*k4.x; acc1[u+1] += v1*k4.y;
                    acc1[u+2] += v1*k4.z; acc1[u+3] += v1*k4.w;
                }
            }
            size_t mb0 = ((size_t)(b*NCB + c))*ODIM*ODIM + i*ODIM + l0;
            size_t mb1 = mb0 + 32*ODIM;
            #pragma unroll
            for (int u = 0; u < 16; u += 4) {
                *(float4*)&g_Mc[mb0 + u] = make_float4(acc0[u], acc0[u+1], acc0[u+2], acc0[u+3]);
                *(float4*)&g_Mc[mb1 + u] = make_float4(acc1[u], acc1[u+1], acc1[u+2], acc1[u+3]);
            }
        }
    }
}

// ---------------- fused phase 2: scan_carry (blocks 0..7) | bind_carry (8..135) ----------------
__global__ void __launch_bounds__(256) phase2()
{
    int bid = blockIdx.x;
    int tid = threadIdx.x;
    if (bid < 8) {
        int b = bid;
        int sd = tid;
        float h = 0.f;
        #pragma unroll 8
        for (int c = 0; c < NCH; c++) {
            int idx = (b*NCH + c)*SDIM + sd;
            g_hpr[idx] = h;
            h = g_sumA[idx]*(h + g_sumB[idx]);
        }
    } else {
        int gid = (bid - 8)*256 + tid;   // 0..32767
        int b = gid >> 12, e = gid & 4095, i = e >> 6;
        float p64 = g_pw[64*ODIM + i];
        float s = 0.f;
        #pragma unroll 8
        for (int c = 0; c < NCB; c++) {
            size_t a = (size_t)b*NCB*4096 + (size_t)c*4096 + e;
            g_Sc[a] = s;
            s = p64*s + g_Mc[a];
        }
    }
}

// ---------------- scan_states ----------------
__global__ void scan_states()
{
    int bc = blockIdx.x;
    int b = bc >> 6, c = bc & 63;
    int sd = threadIdx.x;
    const float* zp = g_Z + ((size_t)(b*TT + c*CHK))*N1 + sd;
    float* op = g_A2 + ((size_t)(b*TT + c*CHK))*KC2 + sd;
    float h = g_hpr[bc*SDIM + sd];
    float rca = 1.f, wb = 0.f;
    #pragma unroll 4
    for (int k = 0; k < CHK; k++) {
        float zg = zp[0];
        float zi = zp[SDIM];
        scan_step(zg, zi, rca, wb);
        *op = tfr(__fdividef(h + wb, rca));
        zp += N1; op += KC2;
    }
}

// ---------------- bind_out (2x t-register-blocked) ----------------
__global__ void bind_out()
{
    extern __shared__ float sm[];
    float* Qs  = sm;            // [64][65]
    float* KT  = sm + 4160;     // [64][64]
    float* SV  = sm + 8256;     // [64][64]
    float* As  = sm + 12352;    // [64][65]
    float* pws = sm + 16512;    // [65][64]
    int b = blockIdx.x >> 5, c = blockIdx.x & 31;
    int tid = threadIdx.x;
    int t = tid >> 2, q0 = (tid & 3)*16;
    size_t zrow = ((size_t)(b*TT + c*CB + t))*N1;
    size_t srow = ((size_t)(b*NCB + c))*4096 + t*ODIM;
    #pragma unroll
    for (int u = 0; u < 4; u++) {
        float4 qv = *(const float4*)&g_Z[zrow + 640 + q0 + u*4];
        Qs[t*65 + q0+u*4+0] = qv.x; Qs[t*65 + q0+u*4+1] = qv.y;
        Qs[t*65 + q0+u*4+2] = qv.z; Qs[t*65 + q0+u*4+3] = qv.w;
        float4 kv = *(const float4*)&g_Z[zrow + 576 + q0 + u*4];
        KT[(q0+u*4+0)*ODIM + t] = kv.x; KT[(q0+u*4+1)*ODIM + t] = kv.y;
        KT[(q0+u*4+2)*ODIM + t] = kv.z; KT[(q0+u*4+3)*ODIM + t] = kv.w;
        float4 sv = *(const float4*)&g_Sc[srow + q0 + u*4];
        SV[(q0+u*4+0)*ODIM + t] = sv.x; SV[(q0+u*4+1)*ODIM + t] = sv.y;
        SV[(q0+u*4+2)*ODIM + t] = sv.z; SV[(q0+u*4+3)*ODIM + t] = sv.w;
    }
    for (int idx = tid; idx < 65*ODIM; idx += 256) pws[idx] = g_pw[idx];
    __syncthreads();

    int t0 = (tid >> 2) & 31;
    float accA0[16], accA1[16], accC0[16], accC1[16];
    if (tid < 128) {
        #pragma unroll
        for (int u = 0; u < 16; u++) { accA0[u]=0.f; accA1[u]=0.f; accC0[u]=0.f; accC1[u]=0.f; }
        for (int l = 0; l < ODIM; l++) {
            float qa = Qs[t0*65 + l];
            float qb = Qs[(t0+32)*65 + l];
            #pragma unroll
            for (int u = 0; u < 16; u += 4) {
                float4 k4 = *(const float4*)&KT[l*ODIM + q0 + u];
                float4 s4 = *(const float4*)&SV[l*ODIM + q0 + u];
                accA0[u+0] += qa*k4.x; accA0[u+1] += qa*k4.y; accA0[u+2] += qa*k4.z; accA0[u+3] += qa*k4.w;
                accA1[u+0] += qb*k4.x; accA1[u+1] += qb*k4.y; accA1[u+2] += qb*k4.z; accA1[u+3] += qb*k4.w;
                accC0[u+0] += qa*s4.x; accC0[u+1] += qa*s4.y; accC0[u+2] += qa*s4.z; accC0[u+3] += qa*s4.w;
                accC1[u+0] += qb*s4.x; accC1[u+1] += qb*s4.y; accC1[u+2] += qb*s4.z; accC1[u+3] += qb*s4.w;
            }
        }
    }
    __syncthreads();
    if (tid < 128) {
        #pragma unroll
        for (int u = 0; u < 16; u++) {
            As[t0*65 + q0 + u]      = accA0[u];
            As[(t0+32)*65 + q0 + u] = accA1[u];
        }
        #pragma unroll
        for (int u = 0; u < 16; u += 4) {
            *(float4*)&KT[t0*ODIM + q0 + u]      = make_float4(accC0[u], accC0[u+1], accC0[u+2], accC0[u+3]);
            *(float4*)&KT[(t0+32)*ODIM + q0 + u] = make_float4(accC1[u], accC1[u+1], accC1[u+2], accC1[u+3]);
        }
    }
    #pragma unroll
    for (int u = 0; u < 4; u++) {
        float4 vv = *(const float4*)&g_Z[zrow + 512 + q0 + u*4];
        *(float4*)&SV[t*ODIM + q0 + u*4] = vv;
    }
    __syncthreads();

    if (tid < 128) {
        int ta = t0, tb = t0 + 32;
        float o0[16], o1[16];
        #pragma unroll
        for (int u = 0; u < 16; u++) {
            o0[u] = pws[(ta+1)*ODIM + q0 + u] * KT[ta*ODIM + q0 + u];
            o1[u] = pws[(tb+1)*ODIM + q0 + u] * KT[tb*ODIM + q0 + u];
        }
        for (int j = 0; j <= tb; j++) {
            float a1 = As[tb*65 + j];
            int d1 = tb - j;
            bool inA = (j <= ta);
            float a0 = inA ? As[ta*65 + j] : 0.f;
            int d0 = inA ? (ta - j) : 0;
            #pragma unroll
            for (int u = 0; u < 16; u += 4) {
                float4 v4  = *(const float4*)&SV[j*ODIM + q0 + u];
                float4 p1v = *(const float4*)&pws[d1*ODIM + q0 + u];
                o1[u+0] += a1*p1v.x*v4.x; o1[u+1] += a1*p1v.y*v4.y;
                o1[u+2] += a1*p1v.z*v4.z; o1[u+3] += a1*p1v.w*v4.w;
                if (inA) {
                    float4 p0v = *(const float4*)&pws[d0*ODIM + q0 + u];
                    o0[u+0] += a0*p0v.x*v4.x; o0[u+1] += a0*p0v.y*v4.y;
                    o0[u+2] += a0*p0v.z*v4.z; o0[u+3] += a0*p0v.w*v4.w;
                }
            }
        }
        size_t orow0 = ((size_t)(b*TT + c*CB + ta))*KC2 + SDIM + q0;
        size_t orow1 = ((size_t)(b*TT + c*CB + tb))*KC2 + SDIM + q0;
        #pragma unroll
        for (int u = 0; u < 16; u += 4) {
            *(float4*)&g_A2[orow0 + u] = make_float4(tfr(o0[u]), tfr(o0[u+1]), tfr(o0[u+2]), tfr(o0[u+3]));
            *(float4*)&g_A2[orow1 + u] = make_float4(tfr(o1[u]), tfr(o1[u+1]), tfr(o1[u+2]), tfr(o1[u+3]));
        }
    }
}

// ---------------- layernorm: warp per row ----------------
__global__ void ln_kernel(const float* __restrict__ lng, const float* __restrict__ lnb,
                          float* __restrict__ out)
{
    int row = blockIdx.x*8 + (threadIdx.x >> 5);
    int lane = threadIdx.x & 31;
    const float4* y4 = (const float4*)(g_Y + (size_t)row*DD);
    float4 v[4];
    float s = 0.f, s2 = 0.f;
    #pragma unroll
    for (int u = 0; u < 4; u++) {
        v[u] = y4[lane + u*32];
        s  += v[u].x + v[u].y + v[u].z + v[u].w;
        s2 += v[u].x*v[u].x + v[u].y*v[u].y + v[u].z*v[u].z + v[u].w*v[u].w;
    }
    #pragma unroll
    for (int off = 16; off; off >>= 1) {
        s  += __shfl_xor_sync(0xffffffffu, s,  off);
        s2 += __shfl_xor_sync(0xffffffffu, s2, off);
    }
    float mu  = s * (1.f/512.f);
    float var = s2 * (1.f/512.f) - mu*mu;
    float inv = rsqrtf(var + 1e-5f);
    float4* o4 = (float4*)(out + (size_t)row*DD);
    const float4* g4 = (const float4*)lng;
    const float4* b4 = (const float4*)lnb;
    #pragma unroll
    for (int u = 0; u < 4; u++) {
        float4 gg = g4[lane + u*32];
        float4 bb = b4[lane + u*32];
        float4 r;
        r.x = (v[u].x - mu)*inv*gg.x + bb.x;
        r.y = (v[u].y - mu)*inv*gg.y + bb.y;
        r.z = (v[u].z - mu)*inv*gg.z + bb.z;
        r.w = (v[u].w - mu)*inv*gg.w + bb.w;
        o4[lane + u*32] = r;
    }
}

// ---------------- host launch ----------------
extern "C" void kernel_launch(void* const* d_in, const int* in_sizes, int n_in,
                              void* d_out, int out_size)
{
    const float* x       = (const float*)d_in[0];
    const float* gate_W  = (const float*)d_in[1];
    const float* gate_b  = (const float*)d_in[2];
    const float* in_W    = (const float*)d_in[3];
    const float* in_b    = (const float*)d_in[4];
    const float* out_W   = (const float*)d_in[5];
    const float* out_b   = (const float*)d_in[6];
    const float* opv_W   = (const float*)d_in[7];
    const float* opv_b   = (const float*)d_in[8];
    const float* opk_W   = (const float*)d_in[9];
    const float* opk_b   = (const float*)d_in[10];
    const float* opq_W   = (const float*)d_in[11];
    const float* opq_b   = (const float*)d_in[12];
    const float* op_decay= (const float*)d_in[13];
    const float* opout_W = (const float*)d_in[14];
    const float* opout_b = (const float*)d_in[15];
    const float* ln_g    = (const float*)d_in[16];
    const float* ln_b    = (const float*)d_in[17];
    float* out = (float*)d_out;

    void *pW1, *pb1, *pZ, *pW2, *pb2, *pA2, *pY;
    cudaGetSymbolAddress(&pW1, g_W1);
    cudaGetSymbolAddress(&pb1, g_b1);
    cudaGetSymbolAddress(&pZ,  g_Z);
    cudaGetSymbolAddress(&pW2, g_W2);
    cudaGetSymbolAddress(&pb2, g_b2);
    cudaGetSymbolAddress(&pA2, g_A2);
    cudaGetSymbolAddress(&pY,  g_Y);

    cudaFuncSetAttribute(gemm_tf32, cudaFuncAttributeMaxDynamicSharedMemorySize, GEMM_SMEM);
    cudaFuncSetAttribute(bind_out, cudaFuncAttributeMaxDynamicSharedMemorySize, 20672*4);

    // prep (fused)
    pack_all<<<2177, 256>>>(gate_W, gate_b, in_W, in_b,
                            opv_W, opv_b, opk_W, opk_b, opq_W, opq_b,
                            out_W, out_b, opout_W, opout_b, op_decay);

    // GEMM-1: Z = x @ W1 + b1
    gemm_tf32<<<dim3(N1/128, MM/128), 256, GEMM_SMEM>>>(
        x, DD, (const float*)pW1, N1, (const float*)pb1,
        nullptr, 0, (float*)pZ, N1, DD);

    // phase 1: gated-scan summaries | binding chunk sums
    phase1<<<768, 256>>>();
    // phase 2: gated-scan carry | binding carry
    phase2<<<136, 256>>>();
    // phase 3
    scan_states<<<BQ*NCH, SDIM>>>();
    bind_out<<<BQ*NCB, 256, 20672*4>>>();

    // GEMM-2: Y = A2 @ W2 + b2 + x
    gemm_tf32<<<dim3(DD/128, MM/128), 256, GEMM_SMEM>>>(
        (const float*)pA2, KC2, (const float*)pW2, DD, (const float*)pb2,
        x, DD, (float*)pY, DD, KC2);

    // layernorm -> out
    ln_kernel<<<MM/8, 256>>>(ln_g, ln_b, out);
}

// round 15
// speedup vs baseline: 1.3886x; 1.0667x over previous
#include <cuda_runtime.h>
#include <math.h>

// Problem constants
#define BQ 8
#define TT 2048
#define DD 512
#define SDIM 256
#define ODIM 64
#define MM (BQ*TT)          // 16384 rows
#define N1 768              // padded 704 (gate 0-255 | in 256-511 | v 512-575 | k 576-639 | q 640-703)
#define KC2 320             // states(256) + bind(64)
#define NCH 64              // scan chunks of 32
#define CHK 32
#define CB 64               // binding chunk
#define NCB 32

// ---------------- device scratch (no runtime allocation) ----------------
__device__ float g_W1[DD*N1];
__device__ float g_b1[N1];
__device__ float g_Z[(size_t)MM*N1];
__device__ float g_W2[KC2*DD];
__device__ float g_b2[DD];
__device__ float g_A2[(size_t)MM*KC2];    // written pre-rounded to tf32
__device__ float g_Y[(size_t)MM*DD];
__device__ float g_sumA[BQ*NCH*SDIM];
__device__ float g_sumB[BQ*NCH*SDIM];
__device__ float g_hpr[BQ*NCH*SDIM];
__device__ float g_Mc[(size_t)BQ*NCB*ODIM*ODIM];
__device__ float g_Sc[(size_t)BQ*NCB*ODIM*ODIM];
__device__ float g_pw[65*ODIM];

__device__ __forceinline__ float sigm_acc(float z){ return 1.0f/(1.0f+expf(-z)); }

__device__ __forceinline__ unsigned f2tf(float x){
    unsigned r; asm("cvt.rna.tf32.f32 %0, %1;" : "=r"(r) : "f"(x)); return r;
}
__device__ __forceinline__ float tfr(float x){ return __uint_as_float(f2tf(x)); }

// ---------------- fused prep kernel ----------------
// blocks [0,1536): W1; [1536,2176): W2; 2176: pw
__global__ void pack_all(const float* __restrict__ gW, const float* __restrict__ gb,
                         const float* __restrict__ iW, const float* __restrict__ ib,
                         const float* __restrict__ vW, const float* __restrict__ vb,
                         const float* __restrict__ kW, const float* __restrict__ kb,
                         const float* __restrict__ qW, const float* __restrict__ qb,
                         const float* __restrict__ oW, const float* __restrict__ ob,
                         const float* __restrict__ pW, const float* __restrict__ pb,
                         const float* __restrict__ op_decay)
{
    int bid = blockIdx.x;
    if (bid < 1536) {
        int idx = bid*256 + threadIdx.x;
        int d = idx / N1, n = idx % N1;
        float w = 0.f;
        if      (n < 256) w = gW[d*256 + n];
        else if (n < 512) w = iW[d*256 + (n-256)];
        else if (n < 576) w = vW[d*64 + (n-512)];
        else if (n < 640) w = kW[d*64 + (n-576)];
        else if (n < 704) w = qW[d*64 + (n-640)];
        g_W1[idx] = tfr(w);
        if (idx < N1) {
            float b = 0.f;
            if      (idx < 256) b = gb[idx];
            else if (idx < 512) b = ib[idx-256];
            else if (idx < 576) b = vb[idx-512];
            else if (idx < 640) b = kb[idx-576];
            else if (idx < 704) b = qb[idx-640];
            g_b1[idx] = b;
        }
    } else if (bid < 2176) {
        int idx = (bid-1536)*256 + threadIdx.x;
        int r = idx / DD, c = idx % DD;
        g_W2[idx] = tfr((r < 256) ? oW[r*DD + c] : pW[(r-256)*DD + c]);
        if (idx < DD) g_b2[idx] = ob[idx] + pb[idx];
    } else {
        int i = threadIdx.x;
        if (i < ODIM) {
            float d = sigm_acc(op_decay[i]);
            float p = 1.f;
            for (int e = 0; e <= 64; e++) { g_pw[e*ODIM + i] = p; p *= d; }
        }
    }
}

// ---------------- tf32 tensor-core GEMM, BK=32 ----------------
#define AST2 36
#define BSTR 136
#define A_BUF_F (128*AST2)          // 4608 floats per buffer
#define B_BUF_F (32*BSTR)           // 4352 floats per buffer
#define GEMM_SMEM ((2*A_BUF_F + 2*B_BUF_F)*4)   // 71680 bytes

__device__ __forceinline__ void mma_tf32(float* c, const unsigned* a, const unsigned* b){
    asm volatile(
      "mma.sync.aligned.m16n8k8.row.col.f32.tf32.tf32.f32 "
      "{%0,%1,%2,%3}, {%4,%5,%6,%7}, {%8,%9}, {%0,%1,%2,%3};\n"
      : "+f"(c[0]), "+f"(c[1]), "+f"(c[2]), "+f"(c[3])
      : "r"(a[0]), "r"(a[1]), "r"(a[2]), "r"(a[3]), "r"(b[0]), "r"(b[1]));
}
__device__ __forceinline__ void cpa16(void* dst, const void* src){
    unsigned d = (unsigned)__cvta_generic_to_shared(dst);
    asm volatile("cp.async.cg.shared.global [%0], [%1], 16;" :: "r"(d), "l"(src));
}

__global__ void __launch_bounds__(256,2) gemm_tf32(
    const float* __restrict__ A, int lda,
    const float* __restrict__ Bw, int ldb,
    const float* __restrict__ bias,
    const float* __restrict__ addsrc, int ldadd,
    float* __restrict__ C, int ldc, int K)
{
    extern __shared__ float sm[];
    // layout: As[2][128][36] | Bs[2][32][136]

    int tid  = threadIdx.x;
    int lane = tid & 31, warp = tid >> 5;
    int wm = (warp >> 2) * 64;
    int wn = (warp & 3) * 32;
    int lr = lane >> 2;
    int lc = lane & 3;

    size_t rowBase = (size_t)blockIdx.y * 128;
    int colBase = blockIdx.x * 128;

    int ar[4], akc[4], bbr[4], bbn[4];
    #pragma unroll
    for (int j = 0; j < 4; j++) {
        int ac = tid + j*256;
        ar[j]  = ac >> 3;  akc[j] = (ac & 7) * 4;
        bbr[j] = ac >> 5;  bbn[j] = (ac & 31) * 4;
    }

    float acc[4][4][4];
    #pragma unroll
    for (int i = 0; i < 4; i++)
        #pragma unroll
        for (int j = 0; j < 4; j++)
            #pragma unroll
            for (int u = 0; u < 4; u++) acc[i][j][u] = 0.f;

    int nIter = K / 32;

    {
        float* Asb = sm;
        float* Bsb = sm + 2*A_BUF_F;
        #pragma unroll
        for (int j = 0; j < 4; j++) {
            cpa16(Asb + ar[j]*AST2 + akc[j], A + (rowBase + ar[j])*lda + akc[j]);
            cpa16(Bsb + bbr[j]*BSTR + bbn[j], Bw + (size_t)bbr[j]*ldb + colBase + bbn[j]);
        }
        asm volatile("cp.async.commit_group;");
    }

    int buf = 0;
    for (int it = 0; it < nIter; it++) {
        asm volatile("cp.async.wait_group 0;");
        __syncthreads();

        if (it + 1 < nIter) {
            int k0 = (it + 1) * 32;
            int nb = buf ^ 1;
            float* Asb = sm + nb*A_BUF_F;
            float* Bsb = sm + 2*A_BUF_F + nb*B_BUF_F;
            #pragma unroll
            for (int j = 0; j < 4; j++) {
                cpa16(Asb + ar[j]*AST2 + akc[j], A + (rowBase + ar[j])*lda + k0 + akc[j]);
                cpa16(Bsb + bbr[j]*BSTR + bbn[j], Bw + (size_t)(k0+bbr[j])*ldb + colBase + bbn[j]);
            }
            asm volatile("cp.async.commit_group;");
        }

        const float* Asb = sm + buf*A_BUF_F;
        const float* Bsb = sm + 2*A_BUF_F + buf*B_BUF_F;

        #pragma unroll
        for (int kk = 0; kk < 32; kk += 8) {
            unsigned af[4][4], bf[4][2];
            #pragma unroll
            for (int mt = 0; mt < 4; mt++) {
                int m0 = wm + mt*16 + lr;
                af[mt][0] = __float_as_uint(Asb[m0*AST2 + kk + lc]);
                af[mt][1] = __float_as_uint(Asb[(m0+8)*AST2 + kk + lc]);
                af[mt][2] = __float_as_uint(Asb[m0*AST2 + kk + lc + 4]);
                af[mt][3] = __float_as_uint(Asb[(m0+8)*AST2 + kk + lc + 4]);
            }
            #pragma unroll
            for (int nt = 0; nt < 4; nt++) {
                int n0 = wn + nt*8 + lr;
                bf[nt][0] = __float_as_uint(Bsb[(kk + lc)*BSTR + n0]);
                bf[nt][1] = __float_as_uint(Bsb[(kk + lc + 4)*BSTR + n0]);
            }
            #pragma unroll
            for (int mt = 0; mt < 4; mt++)
                #pragma unroll
                for (int nt = 0; nt < 4; nt++)
                    mma_tf32(acc[mt][nt], af[mt], bf[nt]);
        }
        buf ^= 1;
    }

    // epilogue
    #pragma unroll
    for (int mt = 0; mt < 4; mt++) {
        size_t row0 = rowBase + wm + mt*16 + lr;
        #pragma unroll
        for (int nt = 0; nt < 4; nt++) {
            int col = colBase + wn + nt*8 + lc*2;
            float b0 = bias[col], b1 = bias[col+1];
            float a00=0.f,a01=0.f,a10=0.f,a11=0.f;
            if (addsrc) {
                const float* p0 = addsrc + row0*(size_t)ldadd + col;
                const float* p1 = addsrc + (row0+8)*(size_t)ldadd + col;
                a00 = p0[0]; a01 = p0[1]; a10 = p1[0]; a11 = p1[1];
            }
            float2 r0 = make_float2(acc[mt][nt][0] + b0 + a00, acc[mt][nt][1] + b1 + a01);
            float2 r1 = make_float2(acc[mt][nt][2] + b0 + a10, acc[mt][nt][3] + b1 + a11);
            *(float2*)(C + row0*(size_t)ldc + col)     = r0;
            *(float2*)(C + (row0+8)*(size_t)ldc + col) = r1;
        }
    }
}

// ---------------- gated scan helpers ----------------
__device__ __forceinline__ void scan_step(float zg, float zi, float& rca, float& wb)
{
    float t = __expf(-zg);
    float rca_new = rca * (1.f + t);
    float c = zi * t * rca;
    if (rca_new > 1e8f) c = zi * t * rca * __fdividef(1e8f, rca_new);
    wb += c;
    rca = rca_new;
}

// ---------------- fused phase 1: scan_summ (blocks 0..511) | bind_chunksum (512..767) ----------------
__global__ void __launch_bounds__(256) phase1()
{
    __shared__ float Vs[CB*ODIM];
    __shared__ float Ks[CB*ODIM];
    int bid = blockIdx.x;
    int tid = threadIdx.x;
    if (bid < 512) {
        // scan_summ
        int b = bid >> 6, c = bid & 63;
        int sd = tid;
        const float* zp = g_Z + ((size_t)(b*TT + c*CHK))*N1 + sd;
        float rca = 1.f, wb = 0.f;
        #pragma unroll 8
        for (int k = 0; k < CHK; k++) {
            float zg = __ldg(zp);
            float zi = __ldg(zp + SDIM);
            scan_step(zg, zi, rca, wb);
            zp += N1;
        }
        int idx = bid*SDIM + sd;
        g_sumA[idx] = __fdividef(1.f, rca);
        g_sumB[idx] = wb;
    } else {
        // bind_chunksum
        int bc = bid - 512;
        int b = bc >> 5, c = bc & 31;
        int j = tid >> 2, q0 = (tid & 3)*16;
        size_t zrow = ((size_t)(b*TT + c*CB + j))*N1;
        #pragma unroll
        for (int u = 0; u < 4; u++) {
            float4 vv = __ldg((const float4*)&g_Z[zrow + 512 + q0 + u*4]);
            float4 pp = __ldg((const float4*)&g_pw[(63-j)*ODIM + q0 + u*4]);
            vv.x *= pp.x; vv.y *= pp.y; vv.z *= pp.z; vv.w *= pp.w;
            *(float4*)&Vs[j*ODIM + q0 + u*4] = vv;
            float4 kk = __ldg((const float4*)&g_Z[zrow + 576 + q0 + u*4]);
            *(float4*)&Ks[j*ODIM + q0 + u*4] = kk;
        }
        __syncthreads();
        if (tid < 128) {
            int i = tid >> 2;
            int l0 = (tid & 3)*16;
            float acc0[16] = {}, acc1[16] = {};
            for (int jj = 0; jj < CB; jj++) {
                float v0 = Vs[jj*ODIM + i];
                float v1 = Vs[jj*ODIM + i + 32];
                #pragma unroll
                for (int u = 0; u < 16; u += 4) {
                    float4 k4 = *(const float4*)&Ks[jj*ODIM + l0 + u];
                    acc0[u+0] += v0*k4.x; acc0[u+1] += v0*k4.y;
                    acc0[u+2] += v0*k4.z; acc0[u+3] += v0*k4.w;
                    acc1[u+0] += v1*k4.x; acc1[u+1] += v1*k4.y;
                    acc1[u+2] += v1*k4.z; acc1[u+3] += v1*k4.w;
                }
            }
            size_t mb0 = ((size_t)(b*NCB + c))*ODIM*ODIM + i*ODIM + l0;
            size_t mb1 = mb0 + 32*ODIM;
            #pragma unroll
            for (int u = 0; u < 16; u += 4) {
                *(float4*)&g_Mc[mb0 + u] = make_float4(acc0[u], acc0[u+1], acc0[u+2], acc0[u+3]);
                *(float4*)&g_Mc[mb1 + u] = make_float4(acc1[u], acc1[u+1], acc1[u+2], acc1[u+3]);
            }
        }
    }
}

// ---------------- fused phase 2: scan_carry (blocks 0..7) | bind_carry (8..135) ----------------
// load-all -> scan-in-registers -> store-all; __ldg breaks false alias dependence
__global__ void __launch_bounds__(256) phase2()
{
    int bid = blockIdx.x;
    int tid = threadIdx.x;
    if (bid < 8) {
        int b = bid;
        int sd = tid;
        float h = 0.f;
        #pragma unroll
        for (int t0 = 0; t0 < NCH; t0 += 16) {
            float Av[16], Bv[16];
            #pragma unroll
            for (int k = 0; k < 16; k++) {
                int idx = (b*NCH + t0 + k)*SDIM + sd;
                Av[k] = __ldg(&g_sumA[idx]);
                Bv[k] = __ldg(&g_sumB[idx]);
            }
            float hp[16];
            #pragma unroll
            for (int k = 0; k < 16; k++) { hp[k] = h; h = Av[k]*(h + Bv[k]); }
            #pragma unroll
            for (int k = 0; k < 16; k++)
                g_hpr[(b*NCH + t0 + k)*SDIM + sd] = hp[k];
        }
    } else {
        int gid = (bid - 8)*256 + tid;   // 0..32767
        int b = gid >> 12, e = gid & 4095, i = e >> 6;
        float p64 = __ldg(&g_pw[64*ODIM + i]);
        size_t base = (size_t)b*NCB*4096 + e;
        float m[NCB];
        #pragma unroll
        for (int c = 0; c < NCB; c++)
            m[c] = __ldg(&g_Mc[base + (size_t)c*4096]);
        float s = 0.f;
        #pragma unroll
        for (int c = 0; c < NCB; c++) {
            g_Sc[base + (size_t)c*4096] = s;
            s = p64*s + m[c];
        }
    }
}

// ---------------- scan_states ----------------
__global__ void scan_states()
{
    int bc = blockIdx.x;
    int b = bc >> 6, c = bc & 63;
    int sd = threadIdx.x;
    const float* zp = g_Z + ((size_t)(b*TT + c*CHK))*N1 + sd;
    float* op = g_A2 + ((size_t)(b*TT + c*CHK))*KC2 + sd;
    float h = g_hpr[bc*SDIM + sd];
    float rca = 1.f, wb = 0.f;
    #pragma unroll 8
    for (int k = 0; k < CHK; k++) {
        float zg = __ldg(zp);
        float zi = __ldg(zp + SDIM);
        scan_step(zg, zi, rca, wb);
        *op = tfr(__fdividef(h + wb, rca));
        zp += N1; op += KC2;
    }
}

// ---------------- bind_out (2x t-register-blocked) ----------------
__global__ void bind_out()
{
    extern __shared__ float sm[];
    float* Qs  = sm;            // [64][65]
    float* KT  = sm + 4160;     // [64][64]
    float* SV  = sm + 8256;     // [64][64]
    float* As  = sm + 12352;    // [64][65]
    float* pws = sm + 16512;    // [65][64]
    int b = blockIdx.x >> 5, c = blockIdx.x & 31;
    int tid = threadIdx.x;
    int t = tid >> 2, q0 = (tid & 3)*16;
    size_t zrow = ((size_t)(b*TT + c*CB + t))*N1;
    size_t srow = ((size_t)(b*NCB + c))*4096 + t*ODIM;
    #pragma unroll
    for (int u = 0; u < 4; u++) {
        float4 qv = __ldg((const float4*)&g_Z[zrow + 640 + q0 + u*4]);
        Qs[t*65 + q0+u*4+0] = qv.x; Qs[t*65 + q0+u*4+1] = qv.y;
        Qs[t*65 + q0+u*4+2] = qv.z; Qs[t*65 + q0+u*4+3] = qv.w;
        float4 kv = __ldg((const float4*)&g_Z[zrow + 576 + q0 + u*4]);
        KT[(q0+u*4+0)*ODIM + t] = kv.x; KT[(q0+u*4+1)*ODIM + t] = kv.y;
        KT[(q0+u*4+2)*ODIM + t] = kv.z; KT[(q0+u*4+3)*ODIM + t] = kv.w;
        float4 sv = __ldg((const float4*)&g_Sc[srow + q0 + u*4]);
        SV[(q0+u*4+0)*ODIM + t] = sv.x; SV[(q0+u*4+1)*ODIM + t] = sv.y;
        SV[(q0+u*4+2)*ODIM + t] = sv.z; SV[(q0+u*4+3)*ODIM + t] = sv.w;
    }
    for (int idx = tid; idx < 65*ODIM; idx += 256) pws[idx] = __ldg(&g_pw[idx]);
    __syncthreads();

    int t0 = (tid >> 2) & 31;
    float accA0[16], accA1[16], accC0[16], accC1[16];
    if (tid < 128) {
        #pragma unroll
        for (int u = 0; u < 16; u++) { accA0[u]=0.f; accA1[u]=0.f; accC0[u]=0.f; accC1[u]=0.f; }
        for (int l = 0; l < ODIM; l++) {
            float qa = Qs[t0*65 + l];
            float qb = Qs[(t0+32)*65 + l];
            #pragma unroll
            for (int u = 0; u < 16; u += 4) {
                float4 k4 = *(const float4*)&KT[l*ODIM + q0 + u];
                float4 s4 = *(const float4*)&SV[l*ODIM + q0 + u];
                accA0[u+0] += qa*k4.x; accA0[u+1] += qa*k4.y; accA0[u+2] += qa*k4.z; accA0[u+3] += qa*k4.w;
                accA1[u+0] += qb*k4.x; accA1[u+1] += qb*k4.y; accA1[u+2] += qb*k4.z; accA1[u+3] += qb*k4.w;
                accC0[u+0] += qa*s4.x; accC0[u+1] += qa*s4.y; accC0[u+2] += qa*s4.z; accC0[u+3] += qa*s4.w;
                accC1[u+0] += qb*s4.x; accC1[u+1] += qb*s4.y; accC1[u+2] += qb*s4.z; accC1[u+3] += qb*s4.w;
            }
        }
    }
    __syncthreads();
    if (tid < 128) {
        #pragma unroll
        for (int u = 0; u < 16; u++) {
            As[t0*65 + q0 + u]      = accA0[u];
            As[(t0+32)*65 + q0 + u] = accA1[u];
        }
        #pragma unroll
        for (int u = 0; u < 16; u += 4) {
            *(float4*)&KT[t0*ODIM + q0 + u]      = make_float4(accC0[u], accC0[u+1], accC0[u+2], accC0[u+3]);
            *(float4*)&KT[(t0+32)*ODIM + q0 + u] = make_float4(accC1[u], accC1[u+1], accC1[u+2], accC1[u+3]);
        }
    }
    #pragma unroll
    for (int u = 0; u < 4; u++) {
        float4 vv = __ldg((const float4*)&g_Z[zrow + 512 + q0 + u*4]);
        *(float4*)&SV[t*ODIM + q0 + u*4] = vv;
    }
    __syncthreads();

    if (tid < 128) {
        int ta = t0, tb = t0 + 32;
        float o0[16], o1[16];
        #pragma unroll
        for (int u = 0; u < 16; u++) {
            o0[u] = pws[(ta+1)*ODIM + q0 + u] * KT[ta*ODIM + q0 + u];
            o1[u] = pws[(tb+1)*ODIM + q0 + u] * KT[tb*ODIM + q0 + u];
        }
        for (int j = 0; j <= tb; j++) {
            float a1 = As[tb*65 + j];
            int d1 = tb - j;
            bool inA = (j <= ta);
            float a0 = inA ? As[ta*65 + j] : 0.f;
            int d0 = inA ? (ta - j) : 0;
            #pragma unroll
            for (int u = 0; u < 16; u += 4) {
                float4 v4  = *(const float4*)&SV[j*ODIM + q0 + u];
                float4 p1v = *(const float4*)&pws[d1*ODIM + q0 + u];
                o1[u+0] += a1*p1v.x*v4.x; o1[u+1] += a1*p1v.y*v4.y;
                o1[u+2] += a1*p1v.z*v4.z; o1[u+3] += a1*p1v.w*v4.w;
                if (inA) {
                    float4 p0v = *(const float4*)&pws[d0*ODIM + q0 + u];
                    o0[u+0] += a0*p0v.x*v4.x; o0[u+1] += a0*p0v.y*v4.y;
                    o0[u+2] += a0*p0v.z*v4.z; o0[u+3] += a0*p0v.w*v4.w;
                }
            }
        }
        size_t orow0 = ((size_t)(b*TT + c*CB + ta))*KC2 + SDIM + q0;
        size_t orow1 = ((size_t)(b*TT + c*CB + tb))*KC2 + SDIM + q0;
        #pragma unroll
        for (int u = 0; u < 16; u += 4) {
            *(float4*)&g_A2[orow0 + u] = make_float4(tfr(o0[u]), tfr(o0[u+1]), tfr(o0[u+2]), tfr(o0[u+3]));
            *(float4*)&g_A2[orow1 + u] = make_float4(tfr(o1[u]), tfr(o1[u+1]), tfr(o1[u+2]), tfr(o1[u+3]));
        }
    }
}

// ---------------- layernorm: warp per row ----------------
__global__ void ln_kernel(const float* __restrict__ lng, const float* __restrict__ lnb,
                          float* __restrict__ out)
{
    int row = blockIdx.x*8 + (threadIdx.x >> 5);
    int lane = threadIdx.x & 31;
    const float4* y4 = (const float4*)(g_Y + (size_t)row*DD);
    float4 v[4];
    float s = 0.f, s2 = 0.f;
    #pragma unroll
    for (int u = 0; u < 4; u++) {
        v[u] = __ldg(y4 + lane + u*32);
        s  += v[u].x + v[u].y + v[u].z + v[u].w;
        s2 += v[u].x*v[u].x + v[u].y*v[u].y + v[u].z*v[u].z + v[u].w*v[u].w;
    }
    #pragma unroll
    for (int off = 16; off; off >>= 1) {
        s  += __shfl_xor_sync(0xffffffffu, s,  off);
        s2 += __shfl_xor_sync(0xffffffffu, s2, off);
    }
    float mu  = s * (1.f/512.f);
    float var = s2 * (1.f/512.f) - mu*mu;
    float inv = rsqrtf(var + 1e-5f);
    float4* o4 = (float4*)(out + (size_t)row*DD);
    const float4* g4 = (const float4*)lng;
    const float4* b4 = (const float4*)lnb;
    #pragma unroll
    for (int u = 0; u < 4; u++) {
        float4 gg = __ldg(g4 + lane + u*32);
        float4 bb = __ldg(b4 + lane + u*32);
        float4 r;
        r.x = (v[u].x - mu)*inv*gg.x + bb.x;
        r.y = (v[u].y - mu)*inv*gg.y + bb.y;
        r.z = (v[u].z - mu)*inv*gg.z + bb.z;
        r.w = (v[u].w - mu)*inv*gg.w + bb.w;
        o4[lane + u*32] = r;
    }
}

// ---------------- host launch ----------------
extern "C" void kernel_launch(void* const* d_in, const int* in_sizes, int n_in,
                              void* d_out, int out_size)
{
    const float* x       = (const float*)d_in[0];
    const float* gate_W  = (const float*)d_in[1];
    const float* gate_b  = (const float*)d_in[2];
    const float* in_W    = (const float*)d_in[3];
    const float* in_b    = (const float*)d_in[4];
    const float* out_W   = (const float*)d_in[5];
    const float* out_b   = (const float*)d_in[6];
    const float* opv_W   = (const float*)d_in[7];
    const float* opv_b   = (const float*)d_in[8];
    const float* opk_W   = (const float*)d_in[9];
    const float* opk_b   = (const float*)d_in[10];
    const float* opq_W   = (const float*)d_in[11];
    const float* opq_b   = (const float*)d_in[12];
    const float* op_decay= (const float*)d_in[13];
    const float* opout_W = (const float*)d_in[14];
    const float* opout_b = (const float*)d_in[15];
    const float* ln_g    = (const float*)d_in[16];
    const float* ln_b    = (const float*)d_in[17];
    float* out = (float*)d_out;

    void *pW1, *pb1, *pZ, *pW2, *pb2, *pA2, *pY;
    cudaGetSymbolAddress(&pW1, g_W1);
    cudaGetSymbolAddress(&pb1, g_b1);
    cudaGetSymbolAddress(&pZ,  g_Z);
    cudaGetSymbolAddress(&pW2, g_W2);
    cudaGetSymbolAddress(&pb2, g_b2);
    cudaGetSymbolAddress(&pA2, g_A2);
    cudaGetSymbolAddress(&pY,  g_Y);

    cudaFuncSetAttribute(gemm_tf32, cudaFuncAttributeMaxDynamicSharedMemorySize, GEMM_SMEM);
    cudaFuncSetAttribute(bind_out, cudaFuncAttributeMaxDynamicSharedMemorySize, 20672*4);

    // prep (fused)
    pack_all<<<2177, 256>>>(gate_W, gate_b, in_W, in_b,
                            opv_W, opv_b, opk_W, opk_b, opq_W, opq_b,
                            out_W, out_b, opout_W, opout_b, op_decay);

    // GEMM-1: Z = x @ W1 + b1
    gemm_tf32<<<dim3(N1/128, MM/128), 256, GEMM_SMEM>>>(
        x, DD, (const float*)pW1, N1, (const float*)pb1,
        nullptr, 0, (float*)pZ, N1, DD);

    // phase 1: gated-scan summaries | binding chunk sums
    phase1<<<768, 256>>>();
    // phase 2: gated-scan carry | binding carry
    phase2<<<136, 256>>>();
    // phase 3
    scan_states<<<BQ*NCH, SDIM>>>();
    bind_out<<<BQ*NCB, 256, 20672*4>>>();

    // GEMM-2: Y = A2 @ W2 + b2 + x
    gemm_tf32<<<dim3(DD/128, MM/128), 256, GEMM_SMEM>>>(
        (const float*)pA2, KC2, (const float*)pW2, DD, (const float*)pb2,
        x, DD, (float*)pY, DD, KC2);

    // layernorm -> out
    ln_kernel<<<MM/8, 256>>>(ln_g, ln_b, out);
}

// round 16
// speedup vs baseline: 1.4420x; 1.0385x over previous
#include <cuda_runtime.h>
#include <math.h>

// Problem constants
#define BQ 8
#define TT 2048
#define DD 512
#define SDIM 256
#define ODIM 64
#define MM (BQ*TT)          // 16384 rows
#define N1 768              // padded 704 (gate 0-255 | in 256-511 | v 512-575 | k 576-639 | q 640-703)
#define KC2 320             // states(256) + bind(64)
#define NCH 64              // scan chunks of 32
#define CHK 32
#define CB 64               // binding chunk
#define NCB 32

// ---------------- device scratch (no runtime allocation) ----------------
__device__ float g_W1[DD*N1];
__device__ float g_b1[N1];
__device__ float g_Z[(size_t)MM*N1];
__device__ float g_W2[KC2*DD];
__device__ float g_b2[DD];
__device__ float g_A2[(size_t)MM*KC2];    // written pre-rounded to tf32
__device__ float g_Y[(size_t)MM*DD];
__device__ float2 g_sumAB[BQ*NCH*SDIM];   // {1/rca, wb} pairs
__device__ float g_hpr[BQ*NCH*SDIM];
__device__ float g_Mc[(size_t)BQ*NCB*ODIM*ODIM];
__device__ float g_Sc[(size_t)BQ*NCB*ODIM*ODIM];
__device__ float g_pw[65*ODIM];

__device__ __forceinline__ float sigm_acc(float z){ return 1.0f/(1.0f+expf(-z)); }

__device__ __forceinline__ unsigned f2tf(float x){
    unsigned r; asm("cvt.rna.tf32.f32 %0, %1;" : "=r"(r) : "f"(x)); return r;
}
__device__ __forceinline__ float tfr(float x){ return __uint_as_float(f2tf(x)); }

// ---------------- fused prep kernel ----------------
// blocks [0,1536): W1; [1536,2176): W2; 2176: pw
__global__ void pack_all(const float* __restrict__ gW, const float* __restrict__ gb,
                         const float* __restrict__ iW, const float* __restrict__ ib,
                         const float* __restrict__ vW, const float* __restrict__ vb,
                         const float* __restrict__ kW, const float* __restrict__ kb,
                         const float* __restrict__ qW, const float* __restrict__ qb,
                         const float* __restrict__ oW, const float* __restrict__ ob,
                         const float* __restrict__ pW, const float* __restrict__ pb,
                         const float* __restrict__ op_decay)
{
    int bid = blockIdx.x;
    if (bid < 1536) {
        int idx = bid*256 + threadIdx.x;
        int d = idx / N1, n = idx % N1;
        float w = 0.f;
        if      (n < 256) w = gW[d*256 + n];
        else if (n < 512) w = iW[d*256 + (n-256)];
        else if (n < 576) w = vW[d*64 + (n-512)];
        else if (n < 640) w = kW[d*64 + (n-576)];
        else if (n < 704) w = qW[d*64 + (n-640)];
        g_W1[idx] = tfr(w);
        if (idx < N1) {
            float b = 0.f;
            if      (idx < 256) b = gb[idx];
            else if (idx < 512) b = ib[idx-256];
            else if (idx < 576) b = vb[idx-512];
            else if (idx < 640) b = kb[idx-576];
            else if (idx < 704) b = qb[idx-640];
            g_b1[idx] = b;
        }
    } else if (bid < 2176) {
        int idx = (bid-1536)*256 + threadIdx.x;
        int r = idx / DD, c = idx % DD;
        g_W2[idx] = tfr((r < 256) ? oW[r*DD + c] : pW[(r-256)*DD + c]);
        if (idx < DD) g_b2[idx] = ob[idx] + pb[idx];
    } else {
        int i = threadIdx.x;
        if (i < ODIM) {
            float d = sigm_acc(op_decay[i]);
            float p = 1.f;
            for (int e = 0; e <= 64; e++) { g_pw[e*ODIM + i] = p; p *= d; }
        }
    }
}

// ---------------- tf32 tensor-core GEMM, BK=32 ----------------
#define AST2 36
#define BSTR 136
#define A_BUF_F (128*AST2)          // 4608 floats per buffer
#define B_BUF_F (32*BSTR)           // 4352 floats per buffer
#define GEMM_SMEM ((2*A_BUF_F + 2*B_BUF_F)*4)   // 71680 bytes

__device__ __forceinline__ void mma_tf32(float* c, const unsigned* a, const unsigned* b){
    asm volatile(
      "mma.sync.aligned.m16n8k8.row.col.f32.tf32.tf32.f32 "
      "{%0,%1,%2,%3}, {%4,%5,%6,%7}, {%8,%9}, {%0,%1,%2,%3};\n"
      : "+f"(c[0]), "+f"(c[1]), "+f"(c[2]), "+f"(c[3])
      : "r"(a[0]), "r"(a[1]), "r"(a[2]), "r"(a[3]), "r"(b[0]), "r"(b[1]));
}
__device__ __forceinline__ void cpa16(void* dst, const void* src){
    unsigned d = (unsigned)__cvta_generic_to_shared(dst);
    asm volatile("cp.async.cg.shared.global [%0], [%1], 16;" :: "r"(d), "l"(src));
}

__global__ void __launch_bounds__(256,2) gemm_tf32(
    const float* __restrict__ A, int lda,
    const float* __restrict__ Bw, int ldb,
    const float* __restrict__ bias,
    const float* __restrict__ addsrc, int ldadd,
    float* __restrict__ C, int ldc, int K)
{
    extern __shared__ float sm[];
    // layout: As[2][128][36] | Bs[2][32][136]

    int tid  = threadIdx.x;
    int lane = tid & 31, warp = tid >> 5;
    int wm = (warp >> 2) * 64;
    int wn = (warp & 3) * 32;
    int lr = lane >> 2;
    int lc = lane & 3;

    size_t rowBase = (size_t)blockIdx.y * 128;
    int colBase = blockIdx.x * 128;

    int ar[4], akc[4], bbr[4], bbn[4];
    #pragma unroll
    for (int j = 0; j < 4; j++) {
        int ac = tid + j*256;
        ar[j]  = ac >> 3;  akc[j] = (ac & 7) * 4;
        bbr[j] = ac >> 5;  bbn[j] = (ac & 31) * 4;
    }

    float acc[4][4][4];
    #pragma unroll
    for (int i = 0; i < 4; i++)
        #pragma unroll
        for (int j = 0; j < 4; j++)
            #pragma unroll
            for (int u = 0; u < 4; u++) acc[i][j][u] = 0.f;

    int nIter = K / 32;

    {
        float* Asb = sm;
        float* Bsb = sm + 2*A_BUF_F;
        #pragma unroll
        for (int j = 0; j < 4; j++) {
            cpa16(Asb + ar[j]*AST2 + akc[j], A + (rowBase + ar[j])*lda + akc[j]);
            cpa16(Bsb + bbr[j]*BSTR + bbn[j], Bw + (size_t)bbr[j]*ldb + colBase + bbn[j]);
        }
        asm volatile("cp.async.commit_group;");
    }

    int buf = 0;
    for (int it = 0; it < nIter; it++) {
        asm volatile("cp.async.wait_group 0;");
        __syncthreads();

        if (it + 1 < nIter) {
            int k0 = (it + 1) * 32;
            int nb = buf ^ 1;
            float* Asb = sm + nb*A_BUF_F;
            float* Bsb = sm + 2*A_BUF_F + nb*B_BUF_F;
            #pragma unroll
            for (int j = 0; j < 4; j++) {
                cpa16(Asb + ar[j]*AST2 + akc[j], A + (rowBase + ar[j])*lda + k0 + akc[j]);
                cpa16(Bsb + bbr[j]*BSTR + bbn[j], Bw + (size_t)(k0+bbr[j])*ldb + colBase + bbn[j]);
            }
            asm volatile("cp.async.commit_group;");
        }

        const float* Asb = sm + buf*A_BUF_F;
        const float* Bsb = sm + 2*A_BUF_F + buf*B_BUF_F;

        #pragma unroll
        for (int kk = 0; kk < 32; kk += 8) {
            unsigned af[4][4], bf[4][2];
            #pragma unroll
            for (int mt = 0; mt < 4; mt++) {
                int m0 = wm + mt*16 + lr;
                af[mt][0] = __float_as_uint(Asb[m0*AST2 + kk + lc]);
                af[mt][1] = __float_as_uint(Asb[(m0+8)*AST2 + kk + lc]);
                af[mt][2] = __float_as_uint(Asb[m0*AST2 + kk + lc + 4]);
                af[mt][3] = __float_as_uint(Asb[(m0+8)*AST2 + kk + lc + 4]);
            }
            #pragma unroll
            for (int nt = 0; nt < 4; nt++) {
                int n0 = wn + nt*8 + lr;
                bf[nt][0] = __float_as_uint(Bsb[(kk + lc)*BSTR + n0]);
                bf[nt][1] = __float_as_uint(Bsb[(kk + lc + 4)*BSTR + n0]);
            }
            #pragma unroll
            for (int mt = 0; mt < 4; mt++)
                #pragma unroll
                for (int nt = 0; nt < 4; nt++)
                    mma_tf32(acc[mt][nt], af[mt], bf[nt]);
        }
        buf ^= 1;
    }

    // epilogue
    #pragma unroll
    for (int mt = 0; mt < 4; mt++) {
        size_t row0 = rowBase + wm + mt*16 + lr;
        #pragma unroll
        for (int nt = 0; nt < 4; nt++) {
            int col = colBase + wn + nt*8 + lc*2;
            float b0 = bias[col], b1 = bias[col+1];
            float a00=0.f,a01=0.f,a10=0.f,a11=0.f;
            if (addsrc) {
                const float* p0 = addsrc + row0*(size_t)ldadd + col;
                const float* p1 = addsrc + (row0+8)*(size_t)ldadd + col;
                a00 = p0[0]; a01 = p0[1]; a10 = p1[0]; a11 = p1[1];
            }
            float2 r0 = make_float2(acc[mt][nt][0] + b0 + a00, acc[mt][nt][1] + b1 + a01);
            float2 r1 = make_float2(acc[mt][nt][2] + b0 + a10, acc[mt][nt][3] + b1 + a11);
            *(float2*)(C + row0*(size_t)ldc + col)     = r0;
            *(float2*)(C + (row0+8)*(size_t)ldc + col) = r1;
        }
    }
}

// ---------------- gated scan helpers ----------------
__device__ __forceinline__ void scan_step(float zg, float zi, float& rca, float& wb)
{
    float t = __expf(-zg);
    float rca_new = rca * (1.f + t);
    float c = zi * t * rca;
    if (rca_new > 1e8f) c = zi * t * rca * __fdividef(1e8f, rca_new);
    wb += c;
    rca = rca_new;
}

// ---------------- fused phase 1: scan_summ (blocks 0..511) | bind_chunksum (512..767) ----------------
__global__ void __launch_bounds__(256) phase1()
{
    __shared__ float Vs[CB*ODIM];
    __shared__ float Ks[CB*ODIM];
    int bid = blockIdx.x;
    int tid = threadIdx.x;
    if (bid < 512) {
        // scan_summ
        int b = bid >> 6, c = bid & 63;
        int sd = tid;
        const float* zp = g_Z + ((size_t)(b*TT + c*CHK))*N1 + sd;
        float rca = 1.f, wb = 0.f;
        #pragma unroll 8
        for (int k = 0; k < CHK; k++) {
            float zg = __ldg(zp);
            float zi = __ldg(zp + SDIM);
            scan_step(zg, zi, rca, wb);
            zp += N1;
        }
        g_sumAB[bid*SDIM + sd] = make_float2(__fdividef(1.f, rca), wb);
    } else {
        // bind_chunksum
        int bc = bid - 512;
        int b = bc >> 5, c = bc & 31;
        int j = tid >> 2, q0 = (tid & 3)*16;
        size_t zrow = ((size_t)(b*TT + c*CB + j))*N1;
        #pragma unroll
        for (int u = 0; u < 4; u++) {
            float4 vv = __ldg((const float4*)&g_Z[zrow + 512 + q0 + u*4]);
            float4 pp = __ldg((const float4*)&g_pw[(63-j)*ODIM + q0 + u*4]);
            vv.x *= pp.x; vv.y *= pp.y; vv.z *= pp.z; vv.w *= pp.w;
            *(float4*)&Vs[j*ODIM + q0 + u*4] = vv;
            float4 kk = __ldg((const float4*)&g_Z[zrow + 576 + q0 + u*4]);
            *(float4*)&Ks[j*ODIM + q0 + u*4] = kk;
        }
        __syncthreads();
        if (tid < 128) {
            int i = tid >> 2;
            int l0 = (tid & 3)*16;
            float acc0[16] = {}, acc1[16] = {};
            for (int jj = 0; jj < CB; jj++) {
                float v0 = Vs[jj*ODIM + i];
                float v1 = Vs[jj*ODIM + i + 32];
                #pragma unroll
                for (int u = 0; u < 16; u += 4) {
                    float4 k4 = *(const float4*)&Ks[jj*ODIM + l0 + u];
                    acc0[u+0] += v0*k4.x; acc0[u+1] += v0*k4.y;
                    acc0[u+2] += v0*k4.z; acc0[u+3] += v0*k4.w;
                    acc1[u+0] += v1*k4.x; acc1[u+1] += v1*k4.y;
                    acc1[u+2] += v1*k4.z; acc1[u+3] += v1*k4.w;
                }
            }
            size_t mb0 = ((size_t)(b*NCB + c))*ODIM*ODIM + i*ODIM + l0;
            size_t mb1 = mb0 + 32*ODIM;
            #pragma unroll
            for (int u = 0; u < 16; u += 4) {
                *(float4*)&g_Mc[mb0 + u] = make_float4(acc0[u], acc0[u+1], acc0[u+2], acc0[u+3]);
                *(float4*)&g_Mc[mb1 + u] = make_float4(acc1[u], acc1[u+1], acc1[u+2], acc1[u+3]);
            }
        }
    }
}

// ---------------- fused phase 2: scan_carry (blocks 0..7) | bind_carry (8..135) ----------------
// load-all -> scan-in-registers -> store-all; launch_bounds(256,1) frees registers
__global__ void __launch_bounds__(256,1) phase2()
{
    int bid = blockIdx.x;
    int tid = threadIdx.x;
    if (bid < 8) {
        int b = bid;
        int sd = tid;
        float h = 0.f;
        #pragma unroll
        for (int t0 = 0; t0 < NCH; t0 += 16) {
            float2 ab[16];
            #pragma unroll
            for (int k = 0; k < 16; k++)
                ab[k] = __ldg(&g_sumAB[(b*NCH + t0 + k)*SDIM + sd]);
            float hp[16];
            #pragma unroll
            for (int k = 0; k < 16; k++) { hp[k] = h; h = ab[k].x*(h + ab[k].y); }
            #pragma unroll
            for (int k = 0; k < 16; k++)
                g_hpr[(b*NCH + t0 + k)*SDIM + sd] = hp[k];
        }
    } else {
        int gid = (bid - 8)*256 + tid;   // 0..32767
        int b = gid >> 12, e = gid & 4095, i = e >> 6;
        float p64 = __ldg(&g_pw[64*ODIM + i]);
        size_t base = (size_t)b*NCB*4096 + e;
        float m[NCB];
        #pragma unroll
        for (int c = 0; c < NCB; c++)
            m[c] = __ldg(&g_Mc[base + (size_t)c*4096]);
        float s = 0.f;
        #pragma unroll
        for (int c = 0; c < NCB; c++) {
            g_Sc[base + (size_t)c*4096] = s;
            s = p64*s + m[c];
        }
    }
}

// ---------------- scan_states ----------------
__global__ void scan_states()
{
    int bc = blockIdx.x;
    int b = bc >> 6, c = bc & 63;
    int sd = threadIdx.x;
    const float* zp = g_Z + ((size_t)(b*TT + c*CHK))*N1 + sd;
    float* op = g_A2 + ((size_t)(b*TT + c*CHK))*KC2 + sd;
    float h = g_hpr[bc*SDIM + sd];
    float rca = 1.f, wb = 0.f;
    #pragma unroll 8
    for (int k = 0; k < CHK; k++) {
        float zg = __ldg(zp);
        float zi = __ldg(zp + SDIM);
        scan_step(zg, zi, rca, wb);
        *op = tfr(__fdividef(h + wb, rca));
        zp += N1; op += KC2;
    }
}

// ---------------- bind_out (2x t-register-blocked) ----------------
__global__ void bind_out()
{
    extern __shared__ float sm[];
    float* Qs  = sm;            // [64][65]
    float* KT  = sm + 4160;     // [64][64]
    float* SV  = sm + 8256;     // [64][64]
    float* As  = sm + 12352;    // [64][65]
    float* pws = sm + 16512;    // [65][64]
    int b = blockIdx.x >> 5, c = blockIdx.x & 31;
    int tid = threadIdx.x;
    int t = tid >> 2, q0 = (tid & 3)*16;
    size_t zrow = ((size_t)(b*TT + c*CB + t))*N1;
    size_t srow = ((size_t)(b*NCB + c))*4096 + t*ODIM;
    #pragma unroll
    for (int u = 0; u < 4; u++) {
        float4 qv = __ldg((const float4*)&g_Z[zrow + 640 + q0 + u*4]);
        Qs[t*65 + q0+u*4+0] = qv.x; Qs[t*65 + q0+u*4+1] = qv.y;
        Qs[t*65 + q0+u*4+2] = qv.z; Qs[t*65 + q0+u*4+3] = qv.w;
        float4 kv = __ldg((const float4*)&g_Z[zrow + 576 + q0 + u*4]);
        KT[(q0+u*4+0)*ODIM + t] = kv.x; KT[(q0+u*4+1)*ODIM + t] = kv.y;
        KT[(q0+u*4+2)*ODIM + t] = kv.z; KT[(q0+u*4+3)*ODIM + t] = kv.w;
        float4 sv = __ldg((const float4*)&g_Sc[srow + q0 + u*4]);
        SV[(q0+u*4+0)*ODIM + t] = sv.x; SV[(q0+u*4+1)*ODIM + t] = sv.y;
        SV[(q0+u*4+2)*ODIM + t] = sv.z; SV[(q0+u*4+3)*ODIM + t] = sv.w;
    }
    for (int idx = tid; idx < 65*ODIM; idx += 256) pws[idx] = __ldg(&g_pw[idx]);
    __syncthreads();

    int t0 = (tid >> 2) & 31;
    float accA0[16], accA1[16], accC0[16], accC1[16];
    if (tid < 128) {
        #pragma unroll
        for (int u = 0; u < 16; u++) { accA0[u]=0.f; accA1[u]=0.f; accC0[u]=0.f; accC1[u]=0.f; }
        for (int l = 0; l < ODIM; l++) {
            float qa = Qs[t0*65 + l];
            float qb = Qs[(t0+32)*65 + l];
            #pragma unroll
            for (int u = 0; u < 16; u += 4) {
                float4 k4 = *(const float4*)&KT[l*ODIM + q0 + u];
                float4 s4 = *(const float4*)&SV[l*ODIM + q0 + u];
                accA0[u+0] += qa*k4.x; accA0[u+1] += qa*k4.y; accA0[u+2] += qa*k4.z; accA0[u+3] += qa*k4.w;
                accA1[u+0] += qb*k4.x; accA1[u+1] += qb*k4.y; accA1[u+2] += qb*k4.z; accA1[u+3] += qb*k4.w;
                accC0[u+0] += qa*s4.x; accC0[u+1] += qa*s4.y; accC0[u+2] += qa*s4.z; accC0[u+3] += qa*s4.w;
                accC1[u+0] += qb*s4.x; accC1[u+1] += qb*s4.y; accC1[u+2] += qb*s4.z; accC1[u+3] += qb*s4.w;
            }
        }
    }
    __syncthreads();
    if (tid < 128) {
        #pragma unroll
        for (int u = 0; u < 16; u++) {
            As[t0*65 + q0 + u]      = accA0[u];
            As[(t0+32)*65 + q0 + u] = accA1[u];
        }
        #pragma unroll
        for (int u = 0; u < 16; u += 4) {
            *(float4*)&KT[t0*ODIM + q0 + u]      = make_float4(accC0[u], accC0[u+1], accC0[u+2], accC0[u+3]);
            *(float4*)&KT[(t0+32)*ODIM + q0 + u] = make_float4(accC1[u], accC1[u+1], accC1[u+2], accC1[u+3]);
        }
    }
    #pragma unroll
    for (int u = 0; u < 4; u++) {
        float4 vv = __ldg((const float4*)&g_Z[zrow + 512 + q0 + u*4]);
        *(float4*)&SV[t*ODIM + q0 + u*4] = vv;
    }
    __syncthreads();

    if (tid < 128) {
        int ta = t0, tb = t0 + 32;
        float o0[16], o1[16];
        #pragma unroll
        for (int u = 0; u < 16; u++) {
            o0[u] = pws[(ta+1)*ODIM + q0 + u] * KT[ta*ODIM + q0 + u];
            o1[u] = pws[(tb+1)*ODIM + q0 + u] * KT[tb*ODIM + q0 + u];
        }
        for (int j = 0; j <= tb; j++) {
            float a1 = As[tb*65 + j];
            int d1 = tb - j;
            bool inA = (j <= ta);
            float a0 = inA ? As[ta*65 + j] : 0.f;
            int d0 = inA ? (ta - j) : 0;
            #pragma unroll
            for (int u = 0; u < 16; u += 4) {
                float4 v4  = *(const float4*)&SV[j*ODIM + q0 + u];
                float4 p1v = *(const float4*)&pws[d1*ODIM + q0 + u];
                o1[u+0] += a1*p1v.x*v4.x; o1[u+1] += a1*p1v.y*v4.y;
                o1[u+2] += a1*p1v.z*v4.z; o1[u+3] += a1*p1v.w*v4.w;
                if (inA) {
                    float4 p0v = *(const float4*)&pws[d0*ODIM + q0 + u];
                    o0[u+0] += a0*p0v.x*v4.x; o0[u+1] += a0*p0v.y*v4.y;
                    o0[u+2] += a0*p0v.z*v4.z; o0[u+3] += a0*p0v.w*v4.w;
                }
            }
        }
        size_t orow0 = ((size_t)(b*TT + c*CB + ta))*KC2 + SDIM + q0;
        size_t orow1 = ((size_t)(b*TT + c*CB + tb))*KC2 + SDIM + q0;
        #pragma unroll
        for (int u = 0; u < 16; u += 4) {
            *(float4*)&g_A2[orow0 + u] = make_float4(tfr(o0[u]), tfr(o0[u+1]), tfr(o0[u+2]), tfr(o0[u+3]));
            *(float4*)&g_A2[orow1 + u] = make_float4(tfr(o1[u]), tfr(o1[u+1]), tfr(o1[u+2]), tfr(o1[u+3]));
        }
    }
}

// ---------------- layernorm: warp per row ----------------
__global__ void ln_kernel(const float* __restrict__ lng, const float* __restrict__ lnb,
                          float* __restrict__ out)
{
    int row = blockIdx.x*8 + (threadIdx.x >> 5);
    int lane = threadIdx.x & 31;
    const float4* y4 = (const float4*)(g_Y + (size_t)row*DD);
    float4 v[4];
    float s = 0.f, s2 = 0.f;
    #pragma unroll
    for (int u = 0; u < 4; u++) {
        v[u] = __ldg(y4 + lane + u*32);
        s  += v[u].x + v[u].y + v[u].z + v[u].w;
        s2 += v[u].x*v[u].x + v[u].y*v[u].y + v[u].z*v[u].z + v[u].w*v[u].w;
    }
    #pragma unroll
    for (int off = 16; off; off >>= 1) {
        s  += __shfl_xor_sync(0xffffffffu, s,  off);
        s2 += __shfl_xor_sync(0xffffffffu, s2, off);
    }
    float mu  = s * (1.f/512.f);
    float var = s2 * (1.f/512.f) - mu*mu;
    float inv = rsqrtf(var + 1e-5f);
    float4* o4 = (float4*)(out + (size_t)row*DD);
    const float4* g4 = (const float4*)lng;
    const float4* b4 = (const float4*)lnb;
    #pragma unroll
    for (int u = 0; u < 4; u++) {
        float4 gg = __ldg(g4 + lane + u*32);
        float4 bb = __ldg(b4 + lane + u*32);
        float4 r;
        r.x = (v[u].x - mu)*inv*gg.x + bb.x;
        r.y = (v[u].y - mu)*inv*gg.y + bb.y;
        r.z = (v[u].z - mu)*inv*gg.z + bb.z;
        r.w = (v[u].w - mu)*inv*gg.w + bb.w;
        o4[lane + u*32] = r;
    }
}

// ---------------- host launch ----------------
extern "C" void kernel_launch(void* const* d_in, const int* in_sizes, int n_in,
                              void* d_out, int out_size)
{
    const float* x       = (const float*)d_in[0];
    const float* gate_W  = (const float*)d_in[1];
    const float* gate_b  = (const float*)d_in[2];
    const float* in_W    = (const float*)d_in[3];
    const float* in_b    = (const float*)d_in[4];
    const float* out_W   = (const float*)d_in[5];
    const float* out_b   = (const float*)d_in[6];
    const float* opv_W   = (const float*)d_in[7];
    const float* opv_b   = (const float*)d_in[8];
    const float* opk_W   = (const float*)d_in[9];
    const float* opk_b   = (const float*)d_in[10];
    const float* opq_W   = (const float*)d_in[11];
    const float* opq_b   = (const float*)d_in[12];
    const float* op_decay= (const float*)d_in[13];
    const float* opout_W = (const float*)d_in[14];
    const float* opout_b = (const float*)d_in[15];
    const float* ln_g    = (const float*)d_in[16];
    const float* ln_b    = (const float*)d_in[17];
    float* out = (float*)d_out;

    void *pW1, *pb1, *pZ, *pW2, *pb2, *pA2, *pY;
    cudaGetSymbolAddress(&pW1, g_W1);
    cudaGetSymbolAddress(&pb1, g_b1);
    cudaGetSymbolAddress(&pZ,  g_Z);
    cudaGetSymbolAddress(&pW2, g_W2);
    cudaGetSymbolAddress(&pb2, g_b2);
    cudaGetSymbolAddress(&pA2, g_A2);
    cudaGetSymbolAddress(&pY,  g_Y);

    cudaFuncSetAttribute(gemm_tf32, cudaFuncAttributeMaxDynamicSharedMemorySize, GEMM_SMEM);
    cudaFuncSetAttribute(bind_out, cudaFuncAttributeMaxDynamicSharedMemorySize, 20672*4);

    // prep (fused)
    pack_all<<<2177, 256>>>(gate_W, gate_b, in_W, in_b,
                            opv_W, opv_b, opk_W, opk_b, opq_W, opq_b,
                            out_W, out_b, opout_W, opout_b, op_decay);

    // GEMM-1: Z = x @ W1 + b1
    gemm_tf32<<<dim3(N1/128, MM/128), 256, GEMM_SMEM>>>(
        x, DD, (const float*)pW1, N1, (const float*)pb1,
        nullptr, 0, (float*)pZ, N1, DD);

    // phase 1: gated-scan summaries | binding chunk sums
    phase1<<<768, 256>>>();
    // phase 2: gated-scan carry | binding carry
    phase2<<<136, 256>>>();
    // phase 3
    scan_states<<<BQ*NCH, SDIM>>>();
    bind_out<<<BQ*NCB, 256, 20672*4>>>();

    // GEMM-2: Y = A2 @ W2 + b2 + x
    gemm_tf32<<<dim3(DD/128, MM/128), 256, GEMM_SMEM>>>(
        (const float*)pA2, KC2, (const float*)pW2, DD, (const float*)pb2,
        x, DD, (float*)pY, DD, KC2);

    // layernorm -> out
    ln_kernel<<<MM/8, 256>>>(ln_g, ln_b, out);
}